// round 1
// baseline (speedup 1.0000x reference)
#include <cuda_runtime.h>
#include <math.h>
#include <stdint.h>

// Problem dims (fixed)
#define Bdim 2
#define Sdim 2048
#define Ddim 1024
#define Hn   16
#define HDdim 64
#define Vdim 50257
#define Mrows (Bdim * Sdim)   // 4096

// ---------------------------------------------------------------------------
// Scratch (device globals — no runtime allocation allowed)
// ---------------------------------------------------------------------------
__device__ float g_h[(size_t)Mrows * Ddim];        // residual stream   16 MB
__device__ float g_x[(size_t)Mrows * Ddim];        // layernorm output  16 MB
__device__ float g_qkv[(size_t)Mrows * 3 * Ddim];  // qkv               48 MB
__device__ float g_ao[(size_t)Mrows * Ddim];       // attention output  16 MB
__device__ float g_fc[(size_t)Mrows * 4 * Ddim];   // mlp hidden        64 MB

// ---------------------------------------------------------------------------
// Embedding: h[b,s,:] = wte[ids[b,s],:] + wpe[s,:]
// ---------------------------------------------------------------------------
__global__ void __launch_bounds__(256) embed_kernel(
    const int* __restrict__ ids, const float* __restrict__ wte,
    const float* __restrict__ wpe, float* __restrict__ h)
{
    int row = blockIdx.x;              // 0..4095 == b*S + s
    int s   = row & (Sdim - 1);
    int id  = ids[row];
    const float4* te = (const float4*)(wte + (size_t)id * Ddim);
    const float4* pe = (const float4*)(wpe + (size_t)s * Ddim);
    float4* out = (float4*)(h + (size_t)row * Ddim);
    int t = threadIdx.x;               // 256 threads, 256 float4 per row
    float4 a = te[t], b = pe[t];
    out[t] = make_float4(a.x + b.x, a.y + b.y, a.z + b.z, a.w + b.w);
}

// ---------------------------------------------------------------------------
// LayerNorm over D=1024, one block (256 threads) per row
// ---------------------------------------------------------------------------
__global__ void __launch_bounds__(256) ln_kernel(
    const float* __restrict__ in, const float* __restrict__ g,
    const float* __restrict__ b, float* __restrict__ out)
{
    int row = blockIdx.x;
    int t = threadIdx.x;
    const float4* xp = (const float4*)(in + (size_t)row * Ddim);
    float4 v = xp[t];
    float s = v.x + v.y + v.z + v.w;
    float q = v.x * v.x + v.y * v.y + v.z * v.z + v.w * v.w;
    __shared__ float rs[8], rq[8];
    #pragma unroll
    for (int o = 16; o > 0; o >>= 1) {
        s += __shfl_xor_sync(0xffffffffu, s, o);
        q += __shfl_xor_sync(0xffffffffu, q, o);
    }
    if ((t & 31) == 0) { rs[t >> 5] = s; rq[t >> 5] = q; }
    __syncthreads();
    if (t == 0) {
        float S = 0.f, Q = 0.f;
        #pragma unroll
        for (int i = 0; i < 8; i++) { S += rs[i]; Q += rq[i]; }
        rs[0] = S; rq[0] = Q;
    }
    __syncthreads();
    float mu   = rs[0] * (1.f / Ddim);
    float var  = rq[0] * (1.f / Ddim) - mu * mu;
    float rstd = rsqrtf(var + 1e-5f);
    float4 gg = ((const float4*)g)[t];
    float4 bb = ((const float4*)b)[t];
    float4 o;
    o.x = (v.x - mu) * rstd * gg.x + bb.x;
    o.y = (v.y - mu) * rstd * gg.y + bb.y;
    o.z = (v.z - mu) * rstd * gg.z + bb.z;
    o.w = (v.w - mu) * rstd * gg.w + bb.w;
    ((float4*)(out + (size_t)row * Ddim))[t] = o;
}

// ---------------------------------------------------------------------------
// GELU (gpt2 "new" tanh form)
// ---------------------------------------------------------------------------
__device__ __forceinline__ float gelu_new_f(float x) {
    float t = tanhf(0.7978845608028654f * (x + 0.044715f * x * x * x));
    return 0.5f * x * (1.0f + t);
}

// guarded B-tile load (handles N not multiple of 4 / tail columns)
__device__ __forceinline__ float4 load_b_tile(const float* __restrict__ B,
                                              int k, int N, int gn, bool nvec)
{
    const float* p = B + (size_t)k * N + gn;
    if (nvec && (gn + 3 < N)) return *(const float4*)p;
    float4 v;
    v.x = (gn + 0 < N) ? p[0] : 0.f;
    v.y = (gn + 1 < N) ? p[1] : 0.f;
    v.z = (gn + 2 < N) ? p[2] : 0.f;
    v.w = (gn + 3 < N) ? p[3] : 0.f;
    return v;
}

// ---------------------------------------------------------------------------
// fp32 GEMM: C[M,N] = A[M,K] @ B[K,N] (+bias) (gelu) (+residual)
// 128x128 tile, BK=8, 256 threads, 8x8 per thread, reg-prefetch pipelining.
// M must be a multiple of 128; K a multiple of 8; N arbitrary (guarded).
// grid = (M/128, ceil(N/128)) — x-major over M so concurrent blocks share B
// tiles in L2 (B is the big streamed operand on the LM head).
// ---------------------------------------------------------------------------
template<bool HAS_BIAS, bool DO_GELU, bool HAS_RES>
__global__ void __launch_bounds__(256) gemm_kernel(
    const float* __restrict__ A, const float* __restrict__ B,
    const float* __restrict__ bias, const float* __restrict__ res,
    float* __restrict__ C, int M, int N, int K)
{
    __shared__ float As[8][128];
    __shared__ float Bs[8][128];

    int tid = threadIdx.x;
    int bm = blockIdx.x * 128;
    int bn = blockIdx.y * 128;

    int arow = tid >> 1;             // 0..127
    int acol = (tid & 1) << 2;       // 0 or 4
    int brow = tid >> 5;             // 0..7
    int bcol = (tid & 31) << 2;      // 0..124
    int ty = (tid >> 4) << 3;        // row offset 0..120
    int tx = (tid & 15) << 3;        // col offset 0..120
    int gn_load = bn + bcol;
    bool nvec = ((N & 3) == 0);

    float acc[8][8];
    #pragma unroll
    for (int i = 0; i < 8; i++)
        #pragma unroll
        for (int j = 0; j < 8; j++) acc[i][j] = 0.f;

    const float* Ap = A + (size_t)(bm + arow) * K + acol;

    // prefetch first K-tile into registers
    float4 av = *(const float4*)Ap;
    float4 bv = load_b_tile(B, brow, N, gn_load, nvec);

    for (int k0 = 0; k0 < K; k0 += 8) {
        As[acol + 0][arow] = av.x;
        As[acol + 1][arow] = av.y;
        As[acol + 2][arow] = av.z;
        As[acol + 3][arow] = av.w;
        *(float4*)&Bs[brow][bcol] = bv;
        __syncthreads();

        if (k0 + 8 < K) {   // prefetch next tile (overlaps with FMA below)
            av = *(const float4*)(Ap + k0 + 8);
            bv = load_b_tile(B, k0 + 8 + brow, N, gn_load, nvec);
        }

        #pragma unroll
        for (int kk = 0; kk < 8; kk++) {
            float4 a0 = *(const float4*)&As[kk][ty];
            float4 a1 = *(const float4*)&As[kk][ty + 4];
            float4 b0 = *(const float4*)&Bs[kk][tx];
            float4 b1 = *(const float4*)&Bs[kk][tx + 4];
            float ar[8] = {a0.x, a0.y, a0.z, a0.w, a1.x, a1.y, a1.z, a1.w};
            float br[8] = {b0.x, b0.y, b0.z, b0.w, b1.x, b1.y, b1.z, b1.w};
            #pragma unroll
            for (int i = 0; i < 8; i++)
                #pragma unroll
                for (int j = 0; j < 8; j++)
                    acc[i][j] += ar[i] * br[j];
        }
        __syncthreads();
    }

    // epilogue
    #pragma unroll
    for (int i = 0; i < 8; i++) {
        size_t rowoff = (size_t)(bm + ty + i) * (size_t)N;
        #pragma unroll
        for (int j = 0; j < 8; j++) {
            int gn = bn + tx + j;
            if (gn < N) {
                float v = acc[i][j];
                if (HAS_BIAS) v += bias[gn];
                if (DO_GELU)  v = gelu_new_f(v);
                if (HAS_RES)  v += res[rowoff + gn];
                C[rowoff + gn] = v;
            }
        }
    }
}

// ---------------------------------------------------------------------------
// Flash attention (causal). HD=64, 64-row Q tile per block, 256 threads.
// Thread t handles q-row r = t/4 and 16 k-columns / 16 output dims (c = t&3).
// Dynamic smem: Q[64][68] + KV[64][68] + P[64][68]  (pad 68 -> conflict-free
// row-broadcast, 16B aligned rows) = 52224 B.
// ---------------------------------------------------------------------------
#define FLASH_PAD 68
#define FLASH_SMEM (3 * 64 * FLASH_PAD * (int)sizeof(float))

__global__ void __launch_bounds__(256) flash_kernel(
    const float* __restrict__ qkv, float* __restrict__ ao)
{
    extern __shared__ float sm[];
    float* Qs  = sm;
    float* KVs = sm + 64 * FLASH_PAD;
    float* Ps  = sm + 2 * 64 * FLASH_PAD;

    int qt  = blockIdx.x;            // 0..31 (q tile)
    int bh  = blockIdx.y;            // 0..31 (b*H + h)
    int b   = bh >> 4;
    int h   = bh & 15;
    int tid = threadIdx.x;
    int r   = tid >> 2;              // q row in tile (0..63)
    int c   = tid & 3;               // column quarter

    const size_t qkv_base = (size_t)b * Sdim * (3 * Ddim) + (size_t)h * HDdim;

    // load Q tile (64x64)
    #pragma unroll
    for (int it = 0; it < 4; it++) {
        int idx = tid + it * 256;
        int rr = idx >> 4;
        int cc = (idx & 15) << 2;
        *(float4*)&Qs[rr * FLASH_PAD + cc] =
            *(const float4*)(qkv + qkv_base + (size_t)(qt * 64 + rr) * (3 * Ddim) + cc);
    }

    float m = -1e30f, l = 0.f;
    float acc[16];
    #pragma unroll
    for (int i = 0; i < 16; i++) acc[i] = 0.f;
    int qglob = qt * 64 + r;

    for (int kt = 0; kt <= qt; kt++) {
        __syncthreads();  // prior PV reads of KVs done; Q writes visible (kt==0)
        // load K tile into KVs
        #pragma unroll
        for (int it = 0; it < 4; it++) {
            int idx = tid + it * 256;
            int rr = idx >> 4;
            int cc = (idx & 15) << 2;
            *(float4*)&KVs[rr * FLASH_PAD + cc] =
                *(const float4*)(qkv + qkv_base + Ddim +
                                 (size_t)(kt * 64 + rr) * (3 * Ddim) + cc);
        }
        __syncthreads();

        // scores: s[i] = dot(Q[r], K[c*16+i]) * 1/sqrt(64)
        float s[16];
        #pragma unroll
        for (int i = 0; i < 16; i++) s[i] = 0.f;
        #pragma unroll
        for (int d4 = 0; d4 < 16; d4++) {
            float4 q4 = *(const float4*)&Qs[r * FLASH_PAD + d4 * 4];
            #pragma unroll
            for (int i = 0; i < 16; i++) {
                float4 k4 = *(const float4*)&KVs[(c * 16 + i) * FLASH_PAD + d4 * 4];
                s[i] += q4.x * k4.x + q4.y * k4.y + q4.z * k4.z + q4.w * k4.w;
            }
        }
        bool diag = (kt == qt);
        float tmax = -1e30f;
        #pragma unroll
        for (int i = 0; i < 16; i++) {
            s[i] *= 0.125f;
            if (diag && (kt * 64 + c * 16 + i) > qglob) s[i] = -1e30f;
            tmax = fmaxf(tmax, s[i]);
        }
        // row max / row sum across the 4 threads of this row (lanes 4r..4r+3)
        tmax = fmaxf(tmax, __shfl_xor_sync(0xffffffffu, tmax, 1));
        tmax = fmaxf(tmax, __shfl_xor_sync(0xffffffffu, tmax, 2));
        float mnew = fmaxf(m, tmax);
        float corr = __expf(m - mnew);
        float psum = 0.f;
        #pragma unroll
        for (int i = 0; i < 16; i++) {
            float p = __expf(s[i] - mnew);
            psum += p;
            Ps[r * FLASH_PAD + c * 16 + i] = p;
        }
        psum += __shfl_xor_sync(0xffffffffu, psum, 1);
        psum += __shfl_xor_sync(0xffffffffu, psum, 2);
        l = l * corr + psum;
        m = mnew;
        #pragma unroll
        for (int i = 0; i < 16; i++) acc[i] *= corr;
        __syncthreads();  // P written, K reads done -> safe to overwrite KVs

        // load V tile into KVs
        #pragma unroll
        for (int it = 0; it < 4; it++) {
            int idx = tid + it * 256;
            int rr = idx >> 4;
            int cc = (idx & 15) << 2;
            *(float4*)&KVs[rr * FLASH_PAD + cc] =
                *(const float4*)(qkv + qkv_base + 2 * Ddim +
                                 (size_t)(kt * 64 + rr) * (3 * Ddim) + cc);
        }
        __syncthreads();

        // PV: acc[d] += sum_k P[r,k] * V[k, c*16+d]
        #pragma unroll 8
        for (int k = 0; k < 64; k++) {
            float p = Ps[r * FLASH_PAD + k];
            const float4* vr = (const float4*)&KVs[k * FLASH_PAD + c * 16];
            float4 v0 = vr[0], v1 = vr[1], v2 = vr[2], v3 = vr[3];
            acc[0]  += p * v0.x; acc[1]  += p * v0.y; acc[2]  += p * v0.z; acc[3]  += p * v0.w;
            acc[4]  += p * v1.x; acc[5]  += p * v1.y; acc[6]  += p * v1.z; acc[7]  += p * v1.w;
            acc[8]  += p * v2.x; acc[9]  += p * v2.y; acc[10] += p * v2.z; acc[11] += p * v2.w;
            acc[12] += p * v3.x; acc[13] += p * v3.y; acc[14] += p * v3.z; acc[15] += p * v3.w;
        }
    }

    float inv = 1.f / l;
    float* out = ao + (size_t)(b * Sdim + qt * 64 + r) * Ddim + h * HDdim + c * 16;
    #pragma unroll
    for (int j = 0; j < 4; j++) {
        float4 o;
        o.x = acc[j * 4 + 0] * inv;
        o.y = acc[j * 4 + 1] * inv;
        o.z = acc[j * 4 + 2] * inv;
        o.w = acc[j * 4 + 3] * inv;
        *(float4*)(out + j * 4) = o;
    }
}

// ---------------------------------------------------------------------------
// Launch sequence
// ---------------------------------------------------------------------------
extern "C" void kernel_launch(void* const* d_in, const int* in_sizes, int n_in,
                              void* d_out, int out_size)
{
    const int*   ids    = (const int*)d_in[0];
    const float* wte    = (const float*)d_in[1];
    const float* wpe    = (const float*)d_in[2];
    const float* ln1_g  = (const float*)d_in[3];
    const float* ln1_b  = (const float*)d_in[4];
    const float* W_attn = (const float*)d_in[5];
    const float* b_attn = (const float*)d_in[6];
    const float* W_ap   = (const float*)d_in[7];
    const float* b_ap   = (const float*)d_in[8];
    const float* ln2_g  = (const float*)d_in[9];
    const float* ln2_b  = (const float*)d_in[10];
    const float* W_fc   = (const float*)d_in[11];
    const float* b_fc   = (const float*)d_in[12];
    const float* W_proj = (const float*)d_in[13];
    const float* b_proj = (const float*)d_in[14];
    const float* lnf_g  = (const float*)d_in[15];
    const float* lnf_b  = (const float*)d_in[16];
    const float* W_lm   = (const float*)d_in[17];
    float* out = (float*)d_out;

    float *h, *x, *qkv, *ao, *fc;
    cudaGetSymbolAddress((void**)&h,   g_h);
    cudaGetSymbolAddress((void**)&x,   g_x);
    cudaGetSymbolAddress((void**)&qkv, g_qkv);
    cudaGetSymbolAddress((void**)&ao,  g_ao);
    cudaGetSymbolAddress((void**)&fc,  g_fc);

    cudaFuncSetAttribute(flash_kernel,
                         cudaFuncAttributeMaxDynamicSharedMemorySize, FLASH_SMEM);

    // h = wte[ids] + wpe
    embed_kernel<<<Mrows, 256>>>(ids, wte, wpe, h);
    // x = ln1(h)
    ln_kernel<<<Mrows, 256>>>(h, ln1_g, ln1_b, x);
    // qkv = x @ W_attn + b_attn           [4096,3072]
    gemm_kernel<true, false, false><<<dim3(32, 24), 256>>>(
        x, W_attn, b_attn, nullptr, qkv, Mrows, 3 * Ddim, Ddim);
    // ao = causal_attention(qkv)
    flash_kernel<<<dim3(32, 32), 256, FLASH_SMEM>>>(qkv, ao);
    // h = h + ao @ W_ap + b_ap
    gemm_kernel<true, false, true><<<dim3(32, 8), 256>>>(
        ao, W_ap, b_ap, h, h, Mrows, Ddim, Ddim);
    // x = ln2(h)
    ln_kernel<<<Mrows, 256>>>(h, ln2_g, ln2_b, x);
    // fc = gelu(x @ W_fc + b_fc)          [4096,4096]
    gemm_kernel<true, true, false><<<dim3(32, 32), 256>>>(
        x, W_fc, b_fc, nullptr, fc, Mrows, 4 * Ddim, Ddim);
    // h = h + fc @ W_proj + b_proj
    gemm_kernel<true, false, true><<<dim3(32, 8), 256>>>(
        fc, W_proj, b_proj, h, h, Mrows, Ddim, 4 * Ddim);
    // x = lnf(h)
    ln_kernel<<<Mrows, 256>>>(h, lnf_g, lnf_b, x);
    // logits = x @ W_lm                   [4096,50257]
    gemm_kernel<false, false, false><<<dim3(32, 393), 256>>>(
        x, W_lm, nullptr, nullptr, out, Mrows, Vdim, Ddim);
}

// round 2
// speedup vs baseline: 2.0643x; 2.0643x over previous
#include <cuda_runtime.h>
#include <math.h>
#include <stdint.h>

// Problem dims (fixed)
#define Bdim 2
#define Sdim 2048
#define Ddim 1024
#define Hn   16
#define HDdim 64
#define Vdim 50257
#define Mrows (Bdim * Sdim)   // 4096

// ---------------------------------------------------------------------------
// Scratch (device globals — no runtime allocation allowed)
// ---------------------------------------------------------------------------
__device__ float g_h[(size_t)Mrows * Ddim];        // residual stream   16 MB
__device__ float g_x[(size_t)Mrows * Ddim];        // layernorm output  16 MB
__device__ float g_qkv[(size_t)Mrows * 3 * Ddim];  // qkv               48 MB
__device__ float g_ao[(size_t)Mrows * Ddim];       // attention output  16 MB
__device__ float g_fc[(size_t)Mrows * 4 * Ddim];   // mlp hidden        64 MB

// ---------------------------------------------------------------------------
// Embedding: h[b,s,:] = wte[ids[b,s],:] + wpe[s,:]
// ---------------------------------------------------------------------------
__global__ void __launch_bounds__(256) embed_kernel(
    const int* __restrict__ ids, const float* __restrict__ wte,
    const float* __restrict__ wpe, float* __restrict__ h)
{
    int row = blockIdx.x;
    int s   = row & (Sdim - 1);
    int id  = ids[row];
    const float4* te = (const float4*)(wte + (size_t)id * Ddim);
    const float4* pe = (const float4*)(wpe + (size_t)s * Ddim);
    float4* out = (float4*)(h + (size_t)row * Ddim);
    int t = threadIdx.x;
    float4 a = te[t], b = pe[t];
    out[t] = make_float4(a.x + b.x, a.y + b.y, a.z + b.z, a.w + b.w);
}

// ---------------------------------------------------------------------------
// LayerNorm over D=1024, one block (256 threads) per row
// ---------------------------------------------------------------------------
__global__ void __launch_bounds__(256) ln_kernel(
    const float* __restrict__ in, const float* __restrict__ g,
    const float* __restrict__ b, float* __restrict__ out)
{
    int row = blockIdx.x;
    int t = threadIdx.x;
    const float4* xp = (const float4*)(in + (size_t)row * Ddim);
    float4 v = xp[t];
    float s = v.x + v.y + v.z + v.w;
    float q = v.x * v.x + v.y * v.y + v.z * v.z + v.w * v.w;
    __shared__ float rs[8], rq[8];
    #pragma unroll
    for (int o = 16; o > 0; o >>= 1) {
        s += __shfl_xor_sync(0xffffffffu, s, o);
        q += __shfl_xor_sync(0xffffffffu, q, o);
    }
    if ((t & 31) == 0) { rs[t >> 5] = s; rq[t >> 5] = q; }
    __syncthreads();
    if (t == 0) {
        float S = 0.f, Q = 0.f;
        #pragma unroll
        for (int i = 0; i < 8; i++) { S += rs[i]; Q += rq[i]; }
        rs[0] = S; rq[0] = Q;
    }
    __syncthreads();
    float mu   = rs[0] * (1.f / Ddim);
    float var  = rq[0] * (1.f / Ddim) - mu * mu;
    float rstd = rsqrtf(var + 1e-5f);
    float4 gg = ((const float4*)g)[t];
    float4 bb = ((const float4*)b)[t];
    float4 o;
    o.x = (v.x - mu) * rstd * gg.x + bb.x;
    o.y = (v.y - mu) * rstd * gg.y + bb.y;
    o.z = (v.z - mu) * rstd * gg.z + bb.z;
    o.w = (v.w - mu) * rstd * gg.w + bb.w;
    ((float4*)(out + (size_t)row * Ddim))[t] = o;
}

__device__ __forceinline__ float gelu_new_f(float x) {
    float t = tanhf(0.7978845608028654f * (x + 0.044715f * x * x * x));
    return 0.5f * x * (1.0f + t);
}

// ---------------------------------------------------------------------------
// TF32 tensor-core GEMM: C[M,N] = A[M,K] @ B[K,N] (+bias)(gelu)(+res)
// 128x128x32 tile, 256 threads (8 warps, 2x4), warp does 64x32 via
// 4x4 grid of mma.sync.m16n8k8.tf32. 2-stage cp.async double buffering.
// A pitch 36 / B pitch 136 in smem -> conflict-free fragment LDS.
// Requirements: M%128==0, K%32==0. N arbitrary (guarded).
// ---------------------------------------------------------------------------
#define BKt 32
#define APITCH 36          // 32 + 4
#define BPITCH 136         // 128 + 8
#define ASTG (128 * APITCH)
#define BSTG (BKt * BPITCH)
#define GEMM_SMEM ((2 * ASTG + 2 * BSTG) * (int)sizeof(float))  // 71680 B

__device__ __forceinline__ uint32_t f2tf32(float x) {
    uint32_t r;
    asm("cvt.rna.tf32.f32 %0, %1;" : "=r"(r) : "f"(x));
    return r;
}

template<bool HAS_BIAS, bool DO_GELU, bool HAS_RES>
__global__ void __launch_bounds__(256) gemm_tf32_kernel(
    const float* __restrict__ A, const float* __restrict__ B,
    const float* __restrict__ bias, const float* __restrict__ res,
    float* __restrict__ C, int M, int N, int K)
{
    extern __shared__ float sm[];
    float* As = sm;                  // [2][128][APITCH]
    float* Bs = sm + 2 * ASTG;       // [2][BKt][BPITCH]

    const int tid  = threadIdx.x;
    const int wid  = tid >> 5;
    const int lane = tid & 31;
    const int wm   = (wid >> 2) * 64;   // warp m offset in tile
    const int wn   = (wid & 3) * 32;    // warp n offset in tile
    const int lr   = lane >> 2;         // 0..7
    const int lc   = lane & 3;          // 0..3
    const int bm   = blockIdx.x * 128;
    const int bn   = blockIdx.y * 128;
    const bool nvec = ((N & 3) == 0);

    float acc[4][4][4];
    #pragma unroll
    for (int i = 0; i < 4; i++)
        #pragma unroll
        for (int j = 0; j < 4; j++)
            #pragma unroll
            for (int k = 0; k < 4; k++) acc[i][j][k] = 0.f;

    // ---- async tile loaders -------------------------------------------
    auto issueA = [&](int k0, int s) {
        #pragma unroll
        for (int i = 0; i < 4; i++) {
            int idx = tid + i * 256;          // 1024 float4
            int row = idx >> 3;
            int c   = (idx & 7) * 4;
            const float* g = A + (size_t)(bm + row) * K + k0 + c;
            uint32_t d = (uint32_t)__cvta_generic_to_shared(
                &As[s * ASTG + row * APITCH + c]);
            asm volatile("cp.async.cg.shared.global [%0], [%1], 16;"
                         :: "r"(d), "l"(g));
        }
    };
    auto issueB = [&](int k0, int s) {
        if (nvec) {
            #pragma unroll
            for (int i = 0; i < 4; i++) {
                int idx = tid + i * 256;      // 1024 float4
                int row = idx >> 5;
                int c   = (idx & 31) * 4;
                int gn  = bn + c;
                int valid = N - gn;           // elements valid at this float4
                int bytes = valid >= 4 ? 16 : (valid > 0 ? valid * 4 : 0);
                const float* g = (bytes > 0)
                    ? B + (size_t)(k0 + row) * N + gn : B;
                uint32_t d = (uint32_t)__cvta_generic_to_shared(
                    &Bs[s * BSTG + row * BPITCH + c]);
                asm volatile("cp.async.cg.shared.global [%0], [%1], 16, %2;"
                             :: "r"(d), "l"(g), "r"(bytes));
            }
        } else {
            // odd N (LM head): rows not 16B aligned -> 4B copies
            #pragma unroll
            for (int i = 0; i < 16; i++) {
                int idx = tid + i * 256;      // 4096 floats
                int row = idx >> 7;
                int c   = idx & 127;
                int gn  = bn + c;
                int bytes = (gn < N) ? 4 : 0;
                const float* g = (bytes > 0)
                    ? B + (size_t)(k0 + row) * N + gn : B;
                uint32_t d = (uint32_t)__cvta_generic_to_shared(
                    &Bs[s * BSTG + row * BPITCH + c]);
                asm volatile("cp.async.ca.shared.global [%0], [%1], 4, %2;"
                             :: "r"(d), "l"(g), "r"(bytes));
            }
        }
    };

    const int nk = K / BKt;
    issueA(0, 0);
    issueB(0, 0);
    asm volatile("cp.async.commit_group;");

    for (int it = 0; it < nk; it++) {
        const int s = it & 1;
        if (it + 1 < nk) {
            issueA((it + 1) * BKt, (it + 1) & 1);
            issueB((it + 1) * BKt, (it + 1) & 1);
            asm volatile("cp.async.commit_group;");
            asm volatile("cp.async.wait_group 1;");
        } else {
            asm volatile("cp.async.wait_group 0;");
        }
        __syncthreads();

        const float* as = &As[s * ASTG];
        const float* bs = &Bs[s * BSTG];

        #pragma unroll
        for (int kk = 0; kk < BKt; kk += 8) {
            uint32_t afr[4][4];
            #pragma unroll
            for (int mt = 0; mt < 4; mt++) {
                int row = wm + mt * 16 + lr;
                const float* p0 = &as[row * APITCH + kk + lc];
                const float* p1 = &as[(row + 8) * APITCH + kk + lc];
                afr[mt][0] = f2tf32(p0[0]);
                afr[mt][1] = f2tf32(p1[0]);
                afr[mt][2] = f2tf32(p0[4]);
                afr[mt][3] = f2tf32(p1[4]);
            }
            uint32_t bfr[4][2];
            #pragma unroll
            for (int nt = 0; nt < 4; nt++) {
                int col = wn + nt * 8 + lr;
                bfr[nt][0] = f2tf32(bs[(kk + lc) * BPITCH + col]);
                bfr[nt][1] = f2tf32(bs[(kk + lc + 4) * BPITCH + col]);
            }
            #pragma unroll
            for (int mt = 0; mt < 4; mt++)
                #pragma unroll
                for (int nt = 0; nt < 4; nt++) {
                    asm volatile(
                        "mma.sync.aligned.m16n8k8.row.col.f32.tf32.tf32.f32 "
                        "{%0,%1,%2,%3}, {%4,%5,%6,%7}, {%8,%9}, {%0,%1,%2,%3};"
                        : "+f"(acc[mt][nt][0]), "+f"(acc[mt][nt][1]),
                          "+f"(acc[mt][nt][2]), "+f"(acc[mt][nt][3])
                        : "r"(afr[mt][0]), "r"(afr[mt][1]),
                          "r"(afr[mt][2]), "r"(afr[mt][3]),
                          "r"(bfr[nt][0]), "r"(bfr[nt][1]));
                }
        }
        __syncthreads();
    }

    // ---- epilogue (scalar stores; N may be odd) ------------------------
    #pragma unroll
    for (int mt = 0; mt < 4; mt++) {
        int row0 = bm + wm + mt * 16 + lr;
        #pragma unroll
        for (int nt = 0; nt < 4; nt++) {
            int col0 = bn + wn + nt * 8 + lc * 2;
            #pragma unroll
            for (int e = 0; e < 4; e++) {
                int row = row0 + (e >= 2 ? 8 : 0);
                int col = col0 + (e & 1);
                if (col < N) {
                    float v = acc[mt][nt][e];
                    if (HAS_BIAS) v += bias[col];
                    if (DO_GELU)  v = gelu_new_f(v);
                    size_t off = (size_t)row * (size_t)N + col;
                    if (HAS_RES)  v += res[off];
                    C[off] = v;
                }
            }
        }
    }
}

// ---------------------------------------------------------------------------
// Flash attention (causal), fp32. HD=64, 64-row Q tile per block, 256 threads.
// ---------------------------------------------------------------------------
#define FLASH_PAD 68
#define FLASH_SMEM (3 * 64 * FLASH_PAD * (int)sizeof(float))

__global__ void __launch_bounds__(256) flash_kernel(
    const float* __restrict__ qkv, float* __restrict__ ao)
{
    extern __shared__ float sm[];
    float* Qs  = sm;
    float* KVs = sm + 64 * FLASH_PAD;
    float* Ps  = sm + 2 * 64 * FLASH_PAD;

    int qt  = blockIdx.x;
    int bh  = blockIdx.y;
    int b   = bh >> 4;
    int h   = bh & 15;
    int tid = threadIdx.x;
    int r   = tid >> 2;
    int c   = tid & 3;

    const size_t qkv_base = (size_t)b * Sdim * (3 * Ddim) + (size_t)h * HDdim;

    #pragma unroll
    for (int it = 0; it < 4; it++) {
        int idx = tid + it * 256;
        int rr = idx >> 4;
        int cc = (idx & 15) << 2;
        *(float4*)&Qs[rr * FLASH_PAD + cc] =
            *(const float4*)(qkv + qkv_base + (size_t)(qt * 64 + rr) * (3 * Ddim) + cc);
    }

    float m = -1e30f, l = 0.f;
    float acc[16];
    #pragma unroll
    for (int i = 0; i < 16; i++) acc[i] = 0.f;
    int qglob = qt * 64 + r;

    for (int kt = 0; kt <= qt; kt++) {
        __syncthreads();
        #pragma unroll
        for (int it = 0; it < 4; it++) {
            int idx = tid + it * 256;
            int rr = idx >> 4;
            int cc = (idx & 15) << 2;
            *(float4*)&KVs[rr * FLASH_PAD + cc] =
                *(const float4*)(qkv + qkv_base + Ddim +
                                 (size_t)(kt * 64 + rr) * (3 * Ddim) + cc);
        }
        __syncthreads();

        float s[16];
        #pragma unroll
        for (int i = 0; i < 16; i++) s[i] = 0.f;
        #pragma unroll
        for (int d4 = 0; d4 < 16; d4++) {
            float4 q4 = *(const float4*)&Qs[r * FLASH_PAD + d4 * 4];
            #pragma unroll
            for (int i = 0; i < 16; i++) {
                float4 k4 = *(const float4*)&KVs[(c * 16 + i) * FLASH_PAD + d4 * 4];
                s[i] += q4.x * k4.x + q4.y * k4.y + q4.z * k4.z + q4.w * k4.w;
            }
        }
        bool diag = (kt == qt);
        float tmax = -1e30f;
        #pragma unroll
        for (int i = 0; i < 16; i++) {
            s[i] *= 0.125f;
            if (diag && (kt * 64 + c * 16 + i) > qglob) s[i] = -1e30f;
            tmax = fmaxf(tmax, s[i]);
        }
        tmax = fmaxf(tmax, __shfl_xor_sync(0xffffffffu, tmax, 1));
        tmax = fmaxf(tmax, __shfl_xor_sync(0xffffffffu, tmax, 2));
        float mnew = fmaxf(m, tmax);
        float corr = __expf(m - mnew);
        float psum = 0.f;
        #pragma unroll
        for (int i = 0; i < 16; i++) {
            float p = __expf(s[i] - mnew);
            psum += p;
            Ps[r * FLASH_PAD + c * 16 + i] = p;
        }
        psum += __shfl_xor_sync(0xffffffffu, psum, 1);
        psum += __shfl_xor_sync(0xffffffffu, psum, 2);
        l = l * corr + psum;
        m = mnew;
        #pragma unroll
        for (int i = 0; i < 16; i++) acc[i] *= corr;
        __syncthreads();

        #pragma unroll
        for (int it = 0; it < 4; it++) {
            int idx = tid + it * 256;
            int rr = idx >> 4;
            int cc = (idx & 15) << 2;
            *(float4*)&KVs[rr * FLASH_PAD + cc] =
                *(const float4*)(qkv + qkv_base + 2 * Ddim +
                                 (size_t)(kt * 64 + rr) * (3 * Ddim) + cc);
        }
        __syncthreads();

        #pragma unroll 8
        for (int k = 0; k < 64; k++) {
            float p = Ps[r * FLASH_PAD + k];
            const float4* vr = (const float4*)&KVs[k * FLASH_PAD + c * 16];
            float4 v0 = vr[0], v1 = vr[1], v2 = vr[2], v3 = vr[3];
            acc[0]  += p * v0.x; acc[1]  += p * v0.y; acc[2]  += p * v0.z; acc[3]  += p * v0.w;
            acc[4]  += p * v1.x; acc[5]  += p * v1.y; acc[6]  += p * v1.z; acc[7]  += p * v1.w;
            acc[8]  += p * v2.x; acc[9]  += p * v2.y; acc[10] += p * v2.z; acc[11] += p * v2.w;
            acc[12] += p * v3.x; acc[13] += p * v3.y; acc[14] += p * v3.z; acc[15] += p * v3.w;
        }
    }

    float inv = 1.f / l;
    float* out = ao + (size_t)(b * Sdim + qt * 64 + r) * Ddim + h * HDdim + c * 16;
    #pragma unroll
    for (int j = 0; j < 4; j++) {
        float4 o;
        o.x = acc[j * 4 + 0] * inv;
        o.y = acc[j * 4 + 1] * inv;
        o.z = acc[j * 4 + 2] * inv;
        o.w = acc[j * 4 + 3] * inv;
        *(float4*)(out + j * 4) = o;
    }
}

// ---------------------------------------------------------------------------
// Launch sequence
// ---------------------------------------------------------------------------
extern "C" void kernel_launch(void* const* d_in, const int* in_sizes, int n_in,
                              void* d_out, int out_size)
{
    const int*   ids    = (const int*)d_in[0];
    const float* wte    = (const float*)d_in[1];
    const float* wpe    = (const float*)d_in[2];
    const float* ln1_g  = (const float*)d_in[3];
    const float* ln1_b  = (const float*)d_in[4];
    const float* W_attn = (const float*)d_in[5];
    const float* b_attn = (const float*)d_in[6];
    const float* W_ap   = (const float*)d_in[7];
    const float* b_ap   = (const float*)d_in[8];
    const float* ln2_g  = (const float*)d_in[9];
    const float* ln2_b  = (const float*)d_in[10];
    const float* W_fc   = (const float*)d_in[11];
    const float* b_fc   = (const float*)d_in[12];
    const float* W_proj = (const float*)d_in[13];
    const float* b_proj = (const float*)d_in[14];
    const float* lnf_g  = (const float*)d_in[15];
    const float* lnf_b  = (const float*)d_in[16];
    const float* W_lm   = (const float*)d_in[17];
    float* out = (float*)d_out;

    float *h, *x, *qkv, *ao, *fc;
    cudaGetSymbolAddress((void**)&h,   g_h);
    cudaGetSymbolAddress((void**)&x,   g_x);
    cudaGetSymbolAddress((void**)&qkv, g_qkv);
    cudaGetSymbolAddress((void**)&ao,  g_ao);
    cudaGetSymbolAddress((void**)&fc,  g_fc);

    cudaFuncSetAttribute(flash_kernel,
                         cudaFuncAttributeMaxDynamicSharedMemorySize, FLASH_SMEM);
    cudaFuncSetAttribute(gemm_tf32_kernel<true, false, false>,
                         cudaFuncAttributeMaxDynamicSharedMemorySize, GEMM_SMEM);
    cudaFuncSetAttribute(gemm_tf32_kernel<true, false, true>,
                         cudaFuncAttributeMaxDynamicSharedMemorySize, GEMM_SMEM);
    cudaFuncSetAttribute(gemm_tf32_kernel<true, true, false>,
                         cudaFuncAttributeMaxDynamicSharedMemorySize, GEMM_SMEM);
    cudaFuncSetAttribute(gemm_tf32_kernel<false, false, false>,
                         cudaFuncAttributeMaxDynamicSharedMemorySize, GEMM_SMEM);

    // h = wte[ids] + wpe
    embed_kernel<<<Mrows, 256>>>(ids, wte, wpe, h);
    // x = ln1(h)
    ln_kernel<<<Mrows, 256>>>(h, ln1_g, ln1_b, x);
    // qkv = x @ W_attn + b_attn           [4096,3072]
    gemm_tf32_kernel<true, false, false><<<dim3(32, 24), 256, GEMM_SMEM>>>(
        x, W_attn, b_attn, nullptr, qkv, Mrows, 3 * Ddim, Ddim);
    // ao = causal_attention(qkv)
    flash_kernel<<<dim3(32, 32), 256, FLASH_SMEM>>>(qkv, ao);
    // h = h + ao @ W_ap + b_ap
    gemm_tf32_kernel<true, false, true><<<dim3(32, 8), 256, GEMM_SMEM>>>(
        ao, W_ap, b_ap, h, h, Mrows, Ddim, Ddim);
    // x = ln2(h)
    ln_kernel<<<Mrows, 256>>>(h, ln2_g, ln2_b, x);
    // fc = gelu(x @ W_fc + b_fc)          [4096,4096]
    gemm_tf32_kernel<true, true, false><<<dim3(32, 32), 256, GEMM_SMEM>>>(
        x, W_fc, b_fc, nullptr, fc, Mrows, 4 * Ddim, Ddim);
    // h = h + fc @ W_proj + b_proj
    gemm_tf32_kernel<true, false, true><<<dim3(32, 8), 256, GEMM_SMEM>>>(
        fc, W_proj, b_proj, h, h, Mrows, Ddim, 4 * Ddim);
    // x = lnf(h)
    ln_kernel<<<Mrows, 256>>>(h, lnf_g, lnf_b, x);
    // logits = x @ W_lm                   [4096,50257]
    gemm_tf32_kernel<false, false, false><<<dim3(32, 393), 256, GEMM_SMEM>>>(
        x, W_lm, nullptr, nullptr, out, Mrows, Vdim, Ddim);
}

// round 5
// speedup vs baseline: 2.5591x; 1.2397x over previous
#include <cuda_runtime.h>
#include <cuda_fp16.h>
#include <math.h>
#include <stdint.h>

// Problem dims (fixed)
#define Bdim 2
#define Sdim 2048
#define Ddim 1024
#define Vdim 50257
#define Mrows (Bdim * Sdim)   // 4096

// ---------------------------------------------------------------------------
// Scratch (device globals — no runtime allocation allowed)
// ---------------------------------------------------------------------------
__device__ float g_h[(size_t)Mrows * Ddim];
__device__ float g_x[(size_t)Mrows * Ddim];
__device__ float g_qkv[(size_t)Mrows * 3 * Ddim];
__device__ float g_ao[(size_t)Mrows * Ddim];
__device__ float g_fc[(size_t)Mrows * 4 * Ddim];

__device__ __forceinline__ float gelu_new_f(float x) {
    float t = tanhf(0.7978845608028654f * (x + 0.044715f * x * x * x));
    return 0.5f * x * (1.0f + t);
}

// ---------------------------------------------------------------------------
// Embedding: h[b,s,:] = wte[ids[b,s],:] + wpe[s,:]
// ---------------------------------------------------------------------------
__global__ void __launch_bounds__(256) embed_kernel(
    const int* __restrict__ ids, const float* __restrict__ wte,
    const float* __restrict__ wpe, float* __restrict__ h)
{
    int row = blockIdx.x;
    int s   = row & (Sdim - 1);
    int id  = ids[row];
    const float4* te = (const float4*)(wte + (size_t)id * Ddim);
    const float4* pe = (const float4*)(wpe + (size_t)s * Ddim);
    float4* out = (float4*)(h + (size_t)row * Ddim);
    int t = threadIdx.x;
    float4 a = te[t], b = pe[t];
    out[t] = make_float4(a.x + b.x, a.y + b.y, a.z + b.z, a.w + b.w);
}

// ---------------------------------------------------------------------------
// LayerNorm over D=1024, one block (256 threads) per row
// ---------------------------------------------------------------------------
__global__ void __launch_bounds__(256) ln_kernel(
    const float* __restrict__ in, const float* __restrict__ g,
    const float* __restrict__ b, float* __restrict__ out)
{
    int row = blockIdx.x;
    int t = threadIdx.x;
    const float4* xp = (const float4*)(in + (size_t)row * Ddim);
    float4 v = xp[t];
    float s = v.x + v.y + v.z + v.w;
    float q = v.x * v.x + v.y * v.y + v.z * v.z + v.w * v.w;
    __shared__ float rs[8], rq[8];
    #pragma unroll
    for (int o = 16; o > 0; o >>= 1) {
        s += __shfl_xor_sync(0xffffffffu, s, o);
        q += __shfl_xor_sync(0xffffffffu, q, o);
    }
    if ((t & 31) == 0) { rs[t >> 5] = s; rq[t >> 5] = q; }
    __syncthreads();
    if (t == 0) {
        float S = 0.f, Q = 0.f;
        #pragma unroll
        for (int i = 0; i < 8; i++) { S += rs[i]; Q += rq[i]; }
        rs[0] = S; rq[0] = Q;
    }
    __syncthreads();
    float mu   = rs[0] * (1.f / Ddim);
    float var  = rq[0] * (1.f / Ddim) - mu * mu;
    float rstd = rsqrtf(var + 1e-5f);
    float4 gg = ((const float4*)g)[t];
    float4 bb = ((const float4*)b)[t];
    float4 o;
    o.x = (v.x - mu) * rstd * gg.x + bb.x;
    o.y = (v.y - mu) * rstd * gg.y + bb.y;
    o.z = (v.z - mu) * rstd * gg.z + bb.z;
    o.w = (v.w - mu) * rstd * gg.w + bb.w;
    ((float4*)(out + (size_t)row * Ddim))[t] = o;
}

// ---------------------------------------------------------------------------
// fp16 tensor-core GEMM (legacy mma.sync m16n8k16, fp32 accumulate).
// C[M,N] = A[M,K] @ W[K,N] (+bias)(gelu)(+res)
// 128x128x32 tile, 256 threads (8 warps 2x4, warp tile 64x32).
// A smem:  half [128][40]    (k contiguous; frag = 1 LDS.32)
// B smem:  half [16][272]    (k-pair interleaved: [(k>>1)][2n + (k&1)];
//                             frag = 1 LDS.32, conflict-free by 272 pitch)
// Register-prefetch pipeline: LDG next k-block during MMA of current.
// Requirements: M%128==0, K%32==0, N arbitrary (guarded).
// ---------------------------------------------------------------------------
#define BK 32
#define AP 40      // A pitch in halves
#define BP 272     // B pitch in halves per k-pair row

template<bool HAS_BIAS, bool DO_GELU, bool HAS_RES>
__global__ void __launch_bounds__(256) gemm_fp16_kernel(
    const float* __restrict__ A, const float* __restrict__ W,
    const float* __restrict__ bias, const float* __restrict__ res,
    float* __restrict__ C, int M, int N, int K)
{
    __shared__ __half As[128 * AP];     // 10240 B
    __shared__ __half Bs[16 * BP];      //  8704 B

    const int tid  = threadIdx.x;
    const int wid  = tid >> 5;
    const int lane = tid & 31;
    const int wm   = (wid >> 2) * 64;
    const int wn   = (wid & 3) * 32;
    const int lr   = lane >> 2;          // 0..7
    const int lc   = lane & 3;           // 0..3
    const int bm   = blockIdx.x * 128;
    const int bn   = blockIdx.y * 256 >> 1;  // keep 128-col tiles
    const int bn128 = blockIdx.y * 128;
    (void)bn;
    const bool neven = ((N & 1) == 0);

    // A loader indices: 4 tasks, task = i*256+tid, m = task>>3, kc = task&7
    const int am = tid >> 3;
    const int akc = tid & 7;
    // B loader indices: task = i*256+tid, kp = task>>6, np = task&63
    const int bkp = tid >> 6;            // 0..3 (+4i)
    const int bnp = tid & 63;

    float acc[4][4][4];
    #pragma unroll
    for (int i = 0; i < 4; i++)
        #pragma unroll
        for (int j = 0; j < 4; j++)
            #pragma unroll
            for (int e = 0; e < 4; e++) acc[i][j][e] = 0.f;

    float4 Ar[4];
    float2 Br0[4], Br1[4];

    auto loadG = [&](int k0) {
        #pragma unroll
        for (int i = 0; i < 4; i++) {
            int m = am + i * 32;
            Ar[i] = *(const float4*)(A + (size_t)(bm + m) * K + k0 + akc * 4);
        }
        #pragma unroll
        for (int i = 0; i < 4; i++) {
            int kp = bkp + i * 4;
            int gn = bn128 + bnp * 2;
            int k  = k0 + kp * 2;
            if (neven && gn + 1 < N) {
                Br0[i] = *(const float2*)(W + (size_t)k * N + gn);
                Br1[i] = *(const float2*)(W + (size_t)(k + 1) * N + gn);
            } else {
                Br0[i].x = (gn     < N) ? W[(size_t)k * N + gn]     : 0.f;
                Br0[i].y = (gn + 1 < N) ? W[(size_t)k * N + gn + 1] : 0.f;
                Br1[i].x = (gn     < N) ? W[(size_t)(k + 1) * N + gn]     : 0.f;
                Br1[i].y = (gn + 1 < N) ? W[(size_t)(k + 1) * N + gn + 1] : 0.f;
            }
        }
    };
    auto storeS = [&]() {
        #pragma unroll
        for (int i = 0; i < 4; i++) {
            int m = am + i * 32;
            __half2* dst = (__half2*)&As[m * AP + akc * 4];
            dst[0] = __float22half2_rn(make_float2(Ar[i].x, Ar[i].y));
            dst[1] = __float22half2_rn(make_float2(Ar[i].z, Ar[i].w));
        }
        #pragma unroll
        for (int i = 0; i < 4; i++) {
            int kp = bkp + i * 4;
            __half2* dst = (__half2*)&Bs[kp * BP + bnp * 4];
            dst[0] = __float22half2_rn(make_float2(Br0[i].x, Br1[i].x));
            dst[1] = __float22half2_rn(make_float2(Br0[i].y, Br1[i].y));
        }
    };

    const int nk = K / BK;
    loadG(0);

    for (int kb = 0; kb < nk; kb++) {
        __syncthreads();           // previous compute done reading smem
        storeS();
        __syncthreads();
        if (kb + 1 < nk) loadG((kb + 1) * BK);   // overlaps with MMAs below

        #pragma unroll
        for (int ks = 0; ks < 2; ks++) {
            const int kk = ks * 16;
            uint32_t afr[4][4];
            #pragma unroll
            for (int mt = 0; mt < 4; mt++) {
                int row = wm + mt * 16 + lr;
                afr[mt][0] = *(const uint32_t*)&As[row * AP + kk + 2 * lc];
                afr[mt][1] = *(const uint32_t*)&As[(row + 8) * AP + kk + 2 * lc];
                afr[mt][2] = *(const uint32_t*)&As[row * AP + kk + 2 * lc + 8];
                afr[mt][3] = *(const uint32_t*)&As[(row + 8) * AP + kk + 2 * lc + 8];
            }
            uint32_t bfr[4][2];
            #pragma unroll
            for (int nt = 0; nt < 4; nt++) {
                int col = wn + nt * 8 + lr;
                int kp0 = (kk >> 1) + lc;        // pair index for k = kk+2lc
                bfr[nt][0] = *(const uint32_t*)&Bs[kp0 * BP + col * 2];
                bfr[nt][1] = *(const uint32_t*)&Bs[(kp0 + 4) * BP + col * 2];
            }
            #pragma unroll
            for (int mt = 0; mt < 4; mt++)
                #pragma unroll
                for (int nt = 0; nt < 4; nt++) {
                    asm volatile(
                        "mma.sync.aligned.m16n8k16.row.col.f32.f16.f16.f32 "
                        "{%0,%1,%2,%3}, {%4,%5,%6,%7}, {%8,%9}, {%0,%1,%2,%3};"
                        : "+f"(acc[mt][nt][0]), "+f"(acc[mt][nt][1]),
                          "+f"(acc[mt][nt][2]), "+f"(acc[mt][nt][3])
                        : "r"(afr[mt][0]), "r"(afr[mt][1]),
                          "r"(afr[mt][2]), "r"(afr[mt][3]),
                          "r"(bfr[nt][0]), "r"(bfr[nt][1]));
                }
        }
    }

    // ---- epilogue ----
    #pragma unroll
    for (int mt = 0; mt < 4; mt++) {
        int row0 = bm + wm + mt * 16 + lr;
        #pragma unroll
        for (int nt = 0; nt < 4; nt++) {
            int col0 = bn128 + wn + nt * 8 + lc * 2;
            #pragma unroll
            for (int e = 0; e < 4; e++) {
                int row = row0 + (e >= 2 ? 8 : 0);
                int col = col0 + (e & 1);
                if (col < N) {
                    float v = acc[mt][nt][e];
                    if (HAS_BIAS) v += bias[col];
                    if (DO_GELU)  v = gelu_new_f(v);
                    size_t off = (size_t)row * (size_t)N + col;
                    if (HAS_RES)  v += res[off];
                    C[off] = v;
                }
            }
        }
    }
}

// ---------------------------------------------------------------------------
// Flash attention (causal), fp32 — unchanged (passes; optimize next round)
// ---------------------------------------------------------------------------
#define FLASH_PAD 68
#define FLASH_SMEM (3 * 64 * FLASH_PAD * (int)sizeof(float))

__global__ void __launch_bounds__(256) flash_kernel(
    const float* __restrict__ qkv, float* __restrict__ ao)
{
    extern __shared__ float sm[];
    float* Qs  = sm;
    float* KVs = sm + 64 * FLASH_PAD;
    float* Ps  = sm + 2 * 64 * FLASH_PAD;

    int qt  = blockIdx.x;
    int bh  = blockIdx.y;
    int b   = bh >> 4;
    int h   = bh & 15;
    int tid = threadIdx.x;
    int r   = tid >> 2;
    int c   = tid & 3;

    const size_t qkv_base = (size_t)b * Sdim * (3 * Ddim) + (size_t)h * 64;

    #pragma unroll
    for (int it = 0; it < 4; it++) {
        int idx = tid + it * 256;
        int rr = idx >> 4;
        int cc = (idx & 15) << 2;
        *(float4*)&Qs[rr * FLASH_PAD + cc] =
            *(const float4*)(qkv + qkv_base + (size_t)(qt * 64 + rr) * (3 * Ddim) + cc);
    }

    float m = -1e30f, l = 0.f;
    float acc[16];
    #pragma unroll
    for (int i = 0; i < 16; i++) acc[i] = 0.f;
    int qglob = qt * 64 + r;

    for (int kt = 0; kt <= qt; kt++) {
        __syncthreads();
        #pragma unroll
        for (int it = 0; it < 4; it++) {
            int idx = tid + it * 256;
            int rr = idx >> 4;
            int cc = (idx & 15) << 2;
            *(float4*)&KVs[rr * FLASH_PAD + cc] =
                *(const float4*)(qkv + qkv_base + Ddim +
                                 (size_t)(kt * 64 + rr) * (3 * Ddim) + cc);
        }
        __syncthreads();

        float s[16];
        #pragma unroll
        for (int i = 0; i < 16; i++) s[i] = 0.f;
        #pragma unroll
        for (int d4 = 0; d4 < 16; d4++) {
            float4 q4 = *(const float4*)&Qs[r * FLASH_PAD + d4 * 4];
            #pragma unroll
            for (int i = 0; i < 16; i++) {
                float4 k4 = *(const float4*)&KVs[(c * 16 + i) * FLASH_PAD + d4 * 4];
                s[i] += q4.x * k4.x + q4.y * k4.y + q4.z * k4.z + q4.w * k4.w;
            }
        }
        bool diag = (kt == qt);
        float tmax = -1e30f;
        #pragma unroll
        for (int i = 0; i < 16; i++) {
            s[i] *= 0.125f;
            if (diag && (kt * 64 + c * 16 + i) > qglob) s[i] = -1e30f;
            tmax = fmaxf(tmax, s[i]);
        }
        tmax = fmaxf(tmax, __shfl_xor_sync(0xffffffffu, tmax, 1));
        tmax = fmaxf(tmax, __shfl_xor_sync(0xffffffffu, tmax, 2));
        float mnew = fmaxf(m, tmax);
        float corr = __expf(m - mnew);
        float psum = 0.f;
        #pragma unroll
        for (int i = 0; i < 16; i++) {
            float p = __expf(s[i] - mnew);
            psum += p;
            Ps[r * FLASH_PAD + c * 16 + i] = p;
        }
        psum += __shfl_xor_sync(0xffffffffu, psum, 1);
        psum += __shfl_xor_sync(0xffffffffu, psum, 2);
        l = l * corr + psum;
        m = mnew;
        #pragma unroll
        for (int i = 0; i < 16; i++) acc[i] *= corr;
        __syncthreads();

        #pragma unroll
        for (int it = 0; it < 4; it++) {
            int idx = tid + it * 256;
            int rr = idx >> 4;
            int cc = (idx & 15) << 2;
            *(float4*)&KVs[rr * FLASH_PAD + cc] =
                *(const float4*)(qkv + qkv_base + 2 * Ddim +
                                 (size_t)(kt * 64 + rr) * (3 * Ddim) + cc);
        }
        __syncthreads();

        #pragma unroll 8
        for (int k = 0; k < 64; k++) {
            float p = Ps[r * FLASH_PAD + k];
            const float4* vr = (const float4*)&KVs[k * FLASH_PAD + c * 16];
            float4 v0 = vr[0], v1 = vr[1], v2 = vr[2], v3 = vr[3];
            acc[0]  += p * v0.x; acc[1]  += p * v0.y; acc[2]  += p * v0.z; acc[3]  += p * v0.w;
            acc[4]  += p * v1.x; acc[5]  += p * v1.y; acc[6]  += p * v1.z; acc[7]  += p * v1.w;
            acc[8]  += p * v2.x; acc[9]  += p * v2.y; acc[10] += p * v2.z; acc[11] += p * v2.w;
            acc[12] += p * v3.x; acc[13] += p * v3.y; acc[14] += p * v3.z; acc[15] += p * v3.w;
        }
    }

    float inv = 1.f / l;
    float* out = ao + (size_t)(b * Sdim + qt * 64 + r) * Ddim + h * 64 + c * 16;
    #pragma unroll
    for (int j = 0; j < 4; j++) {
        float4 o;
        o.x = acc[j * 4 + 0] * inv;
        o.y = acc[j * 4 + 1] * inv;
        o.z = acc[j * 4 + 2] * inv;
        o.w = acc[j * 4 + 3] * inv;
        *(float4*)(out + j * 4) = o;
    }
}

// ---------------------------------------------------------------------------
// Launch sequence
// ---------------------------------------------------------------------------
extern "C" void kernel_launch(void* const* d_in, const int* in_sizes, int n_in,
                              void* d_out, int out_size)
{
    const int*   ids    = (const int*)d_in[0];
    const float* wte    = (const float*)d_in[1];
    const float* wpe    = (const float*)d_in[2];
    const float* ln1_g  = (const float*)d_in[3];
    const float* ln1_b  = (const float*)d_in[4];
    const float* W_attn = (const float*)d_in[5];
    const float* b_attn = (const float*)d_in[6];
    const float* W_ap   = (const float*)d_in[7];
    const float* b_ap   = (const float*)d_in[8];
    const float* ln2_g  = (const float*)d_in[9];
    const float* ln2_b  = (const float*)d_in[10];
    const float* W_fc   = (const float*)d_in[11];
    const float* b_fc   = (const float*)d_in[12];
    const float* W_proj = (const float*)d_in[13];
    const float* b_proj = (const float*)d_in[14];
    const float* lnf_g  = (const float*)d_in[15];
    const float* lnf_b  = (const float*)d_in[16];
    const float* W_lm   = (const float*)d_in[17];
    float* out = (float*)d_out;

    float *h, *x, *qkv, *ao, *fc;
    cudaGetSymbolAddress((void**)&h,   g_h);
    cudaGetSymbolAddress((void**)&x,   g_x);
    cudaGetSymbolAddress((void**)&qkv, g_qkv);
    cudaGetSymbolAddress((void**)&ao,  g_ao);
    cudaGetSymbolAddress((void**)&fc,  g_fc);

    cudaFuncSetAttribute(flash_kernel,
                         cudaFuncAttributeMaxDynamicSharedMemorySize, FLASH_SMEM);

    embed_kernel<<<Mrows, 256>>>(ids, wte, wpe, h);
    ln_kernel<<<Mrows, 256>>>(h, ln1_g, ln1_b, x);
    gemm_fp16_kernel<true, false, false><<<dim3(32, 24), 256>>>(
        x, W_attn, b_attn, nullptr, qkv, Mrows, 3 * Ddim, Ddim);
    flash_kernel<<<dim3(32, 32), 256, FLASH_SMEM>>>(qkv, ao);
    gemm_fp16_kernel<true, false, true><<<dim3(32, 8), 256>>>(
        ao, W_ap, b_ap, h, h, Mrows, Ddim, Ddim);
    ln_kernel<<<Mrows, 256>>>(h, ln2_g, ln2_b, x);
    gemm_fp16_kernel<true, true, false><<<dim3(32, 32), 256>>>(
        x, W_fc, b_fc, nullptr, fc, Mrows, 4 * Ddim, Ddim);
    gemm_fp16_kernel<true, false, true><<<dim3(32, 8), 256>>>(
        fc, W_proj, b_proj, h, h, Mrows, Ddim, 4 * Ddim);
    ln_kernel<<<Mrows, 256>>>(h, lnf_g, lnf_b, x);
    gemm_fp16_kernel<false, false, false><<<dim3(32, 393), 256>>>(
        x, W_lm, nullptr, nullptr, out, Mrows, Vdim, Ddim);
}

// round 6
// speedup vs baseline: 2.9847x; 1.1663x over previous
#include <cuda_runtime.h>
#include <cuda_fp16.h>
#include <math.h>
#include <stdint.h>

// Problem dims (fixed)
#define Bdim 2
#define Sdim 2048
#define Ddim 1024
#define Vdim 50257
#define VPAD 50304            // 393*128, multiple of 8
#define Mrows (Bdim * Sdim)   // 4096

// ---------------------------------------------------------------------------
// Scratch (device globals — no runtime allocation allowed)
// ---------------------------------------------------------------------------
__device__ float  g_h[(size_t)Mrows * Ddim];           // residual (fp32)
__device__ float  g_qkv[(size_t)Mrows * 3 * Ddim];     // qkv (fp32, flash in)
__device__ __half g_x16[(size_t)Mrows * Ddim];         // LN out
__device__ __half g_ao16[(size_t)Mrows * Ddim];        // attn out
__device__ __half g_fc16[(size_t)Mrows * 4 * Ddim];    // gelu out
__device__ __half g_wattn16[(size_t)Ddim * 3 * Ddim];
__device__ __half g_wap16[(size_t)Ddim * Ddim];
__device__ __half g_wfc16[(size_t)Ddim * 4 * Ddim];
__device__ __half g_wproj16[(size_t)4 * Ddim * Ddim];
__device__ __half g_wlm16[(size_t)Ddim * VPAD];

__device__ __forceinline__ uint32_t smem_u32(const void* p) {
    uint32_t a;
    asm("{ .reg .u64 t; cvta.to.shared.u64 t, %1; cvt.u32.u64 %0, t; }"
        : "=r"(a) : "l"(p));
    return a;
}
__device__ __forceinline__ float gelu_new_f(float x) {
    float t = tanhf(0.7978845608028654f * (x + 0.044715f * x * x * x));
    return 0.5f * x * (1.0f + t);
}

// ---------------------------------------------------------------------------
// fp32 -> fp16 weight conversion with optional column padding (zero fill)
// grid = (ceil(Np/2048), K), block 256; each thread converts 8 elements
// ---------------------------------------------------------------------------
__global__ void __launch_bounds__(256) conv16_kernel(
    const float* __restrict__ src, __half* __restrict__ dst, int N, int Np)
{
    int k   = blockIdx.y;
    int col = (blockIdx.x * 256 + threadIdx.x) * 8;
    if (col >= Np) return;
    __half h[8];
    #pragma unroll
    for (int j = 0; j < 8; j++) {
        int n = col + j;
        h[j] = (n < N) ? __float2half_rn(src[(size_t)k * N + n]) : __half(0.f);
    }
    *(uint4*)(dst + (size_t)k * Np + col) = *(uint4*)h;
}

// ---------------------------------------------------------------------------
// Embedding: h[b,s,:] = wte[ids[b,s],:] + wpe[s,:]  (fp32)
// ---------------------------------------------------------------------------
__global__ void __launch_bounds__(256) embed_kernel(
    const int* __restrict__ ids, const float* __restrict__ wte,
    const float* __restrict__ wpe, float* __restrict__ h)
{
    int row = blockIdx.x;
    int s   = row & (Sdim - 1);
    int id  = ids[row];
    const float4* te = (const float4*)(wte + (size_t)id * Ddim);
    const float4* pe = (const float4*)(wpe + (size_t)s * Ddim);
    float4* out = (float4*)(h + (size_t)row * Ddim);
    int t = threadIdx.x;
    float4 a = te[t], b = pe[t];
    out[t] = make_float4(a.x + b.x, a.y + b.y, a.z + b.z, a.w + b.w);
}

// ---------------------------------------------------------------------------
// LayerNorm (fp32 in) -> fp16 out. One block (256 thr) per row, D=1024.
// ---------------------------------------------------------------------------
__global__ void __launch_bounds__(256) ln16_kernel(
    const float* __restrict__ in, const float* __restrict__ g,
    const float* __restrict__ b, __half* __restrict__ out)
{
    int row = blockIdx.x;
    int t = threadIdx.x;
    const float4* xp = (const float4*)(in + (size_t)row * Ddim);
    float4 v = xp[t];
    float s = v.x + v.y + v.z + v.w;
    float q = v.x * v.x + v.y * v.y + v.z * v.z + v.w * v.w;
    __shared__ float rs[8], rq[8];
    #pragma unroll
    for (int o = 16; o > 0; o >>= 1) {
        s += __shfl_xor_sync(0xffffffffu, s, o);
        q += __shfl_xor_sync(0xffffffffu, q, o);
    }
    if ((t & 31) == 0) { rs[t >> 5] = s; rq[t >> 5] = q; }
    __syncthreads();
    if (t == 0) {
        float S = 0.f, Q = 0.f;
        #pragma unroll
        for (int i = 0; i < 8; i++) { S += rs[i]; Q += rq[i]; }
        rs[0] = S; rq[0] = Q;
    }
    __syncthreads();
    float mu   = rs[0] * (1.f / Ddim);
    float var  = rq[0] * (1.f / Ddim) - mu * mu;
    float rstd = rsqrtf(var + 1e-5f);
    float4 gg = ((const float4*)g)[t];
    float4 bb = ((const float4*)b)[t];
    __half2* o = (__half2*)(out + (size_t)row * Ddim + t * 4);
    o[0] = __floats2half2_rn((v.x - mu) * rstd * gg.x + bb.x,
                             (v.y - mu) * rstd * gg.y + bb.y);
    o[1] = __floats2half2_rn((v.z - mu) * rstd * gg.z + bb.z,
                             (v.w - mu) * rstd * gg.w + bb.w);
}

// ---------------------------------------------------------------------------
// fp16 tensor-core GEMM, fully pipelined.
// C[M,N] = A16[M,K] @ W16[K,ldw] (+bias)(gelu)(+res), C fp32 or fp16.
// 128x128x32 tile, 256 threads (8 warps 2x4, warp 64x32), 3-stage cp.async,
// ldmatrix.x4 (A) / ldmatrix.x4.trans (B).
// A smem [128][40] halves; B smem [32][136] halves (k rows, n contiguous).
// M%128==0, K%32==0; W padded so bn+128 <= ldw (no B guards).
// ---------------------------------------------------------------------------
#define APh 40
#define BPh 136
#define ASZ (128 * APh)          // 5120 halves
#define BSZ (32 * BPh)           // 4352 halves
#define STGh (ASZ + BSZ)         // 9472 halves
#define GSMEM (3 * STGh * 2)     // 56832 bytes

#define LDSM4(r0, r1, r2, r3, a) \
    asm volatile("ldmatrix.sync.aligned.m8n8.x4.shared.b16 {%0,%1,%2,%3}, [%4];" \
        : "=r"(r0), "=r"(r1), "=r"(r2), "=r"(r3) : "r"(a))
#define LDSM4T(r0, r1, r2, r3, a) \
    asm volatile("ldmatrix.sync.aligned.m8n8.x4.trans.shared.b16 {%0,%1,%2,%3}, [%4];" \
        : "=r"(r0), "=r"(r1), "=r"(r2), "=r"(r3) : "r"(a))

template<bool HAS_BIAS, bool DO_GELU, bool HAS_RES, bool OUT16>
__global__ void __launch_bounds__(256, 2) gemm16_kernel(
    const __half* __restrict__ A, const __half* __restrict__ W,
    const float* __restrict__ bias, const float* __restrict__ res,
    void* __restrict__ Cv, int M, int N, int K, int ldw)
{
    extern __shared__ __half sh[];
    const uint32_t sb = smem_u32(sh);

    const int tid  = threadIdx.x;
    const int wid  = tid >> 5;
    const int lane = tid & 31;
    const int wm   = (wid >> 2) * 64;
    const int wn   = (wid & 3) * 32;
    const int lr   = lane >> 2;
    const int lc   = lane & 3;
    const int bm   = blockIdx.x * 128;
    const int bn   = blockIdx.y * 128;

    // loader indices
    const int am  = tid >> 2, akc = tid & 3;      // A: 2 iters of (m, chunk)
    const int bk  = tid >> 4, bnc = tid & 15;     // B: 2 iters of (k, chunk)

    auto issue = [&](int kb) {
        const int s = kb % 3;
        const uint32_t as = sb + (uint32_t)(s * STGh) * 2;
        const uint32_t bs = as + ASZ * 2;
        const int k0 = kb * 32;
        #pragma unroll
        for (int i = 0; i < 2; i++) {
            int m = am + i * 64;
            const __half* src = A + (size_t)(bm + m) * K + k0 + akc * 8;
            uint32_t dst = as + (uint32_t)(m * APh + akc * 8) * 2;
            asm volatile("cp.async.cg.shared.global [%0], [%1], 16;"
                         :: "r"(dst), "l"(src));
        }
        #pragma unroll
        for (int i = 0; i < 2; i++) {
            int k = bk + i * 16;
            const __half* src = W + (size_t)(k0 + k) * ldw + bn + bnc * 8;
            uint32_t dst = bs + (uint32_t)(k * BPh + bnc * 8) * 2;
            asm volatile("cp.async.cg.shared.global [%0], [%1], 16;"
                         :: "r"(dst), "l"(src));
        }
        asm volatile("cp.async.commit_group;");
    };

    float acc[4][4][4];
    #pragma unroll
    for (int i = 0; i < 4; i++)
        #pragma unroll
        for (int j = 0; j < 4; j++)
            #pragma unroll
            for (int e = 0; e < 4; e++) acc[i][j][e] = 0.f;

    const int nk = K / 32;
    issue(0);
    issue(1);

    for (int kb = 0; kb < nk; kb++) {
        if (kb + 1 < nk) asm volatile("cp.async.wait_group 1;");
        else             asm volatile("cp.async.wait_group 0;");
        __syncthreads();
        if (kb + 2 < nk) issue(kb + 2);

        const int s = kb % 3;
        const uint32_t as = sb + (uint32_t)(s * STGh) * 2;
        const uint32_t bs = as + ASZ * 2;

        #pragma unroll
        for (int ks = 0; ks < 2; ks++) {
            const int kk = ks * 16;
            uint32_t afr[4][4];
            #pragma unroll
            for (int mt = 0; mt < 4; mt++) {
                uint32_t a = as + (uint32_t)((wm + mt * 16 + (lane & 15)) * APh
                                             + kk + 8 * (lane >> 4)) * 2;
                LDSM4(afr[mt][0], afr[mt][1], afr[mt][2], afr[mt][3], a);
            }
            uint32_t bfr[4][2];
            #pragma unroll
            for (int p = 0; p < 2; p++) {
                int ntp = p * 2;
                uint32_t a = bs + (uint32_t)((kk + (lane & 7) + 8 * ((lane >> 3) & 1)) * BPh
                                             + wn + (ntp + (lane >> 4)) * 8) * 2;
                LDSM4T(bfr[ntp][0], bfr[ntp][1], bfr[ntp + 1][0], bfr[ntp + 1][1], a);
            }
            #pragma unroll
            for (int mt = 0; mt < 4; mt++)
                #pragma unroll
                for (int nt = 0; nt < 4; nt++) {
                    asm volatile(
                        "mma.sync.aligned.m16n8k16.row.col.f32.f16.f16.f32 "
                        "{%0,%1,%2,%3}, {%4,%5,%6,%7}, {%8,%9}, {%0,%1,%2,%3};"
                        : "+f"(acc[mt][nt][0]), "+f"(acc[mt][nt][1]),
                          "+f"(acc[mt][nt][2]), "+f"(acc[mt][nt][3])
                        : "r"(afr[mt][0]), "r"(afr[mt][1]),
                          "r"(afr[mt][2]), "r"(afr[mt][3]),
                          "r"(bfr[nt][0]), "r"(bfr[nt][1]));
                }
        }
    }

    // ---- epilogue ----
    float* Cf = (float*)Cv;
    __half* Ch = (__half*)Cv;
    #pragma unroll
    for (int mt = 0; mt < 4; mt++) {
        int row0 = bm + wm + mt * 16 + lr;
        #pragma unroll
        for (int nt = 0; nt < 4; nt++) {
            int col0 = bn + wn + nt * 8 + lc * 2;
            #pragma unroll
            for (int e = 0; e < 4; e++) {
                int row = row0 + (e >= 2 ? 8 : 0);
                int col = col0 + (e & 1);
                if (col < N) {
                    float v = acc[mt][nt][e];
                    if (HAS_BIAS) v += bias[col];
                    if (DO_GELU)  v = gelu_new_f(v);
                    size_t off = (size_t)row * (size_t)N + col;
                    if (HAS_RES)  v += res[off];
                    if (OUT16) Ch[off] = __float2half_rn(v);
                    else       Cf[off] = v;
                }
            }
        }
    }
}

// ---------------------------------------------------------------------------
// Flash attention (causal), fp32 math, fp16 output. 64-row Q tile, 256 thr.
// ---------------------------------------------------------------------------
#define FLASH_PAD 68
#define FLASH_SMEM (3 * 64 * FLASH_PAD * (int)sizeof(float))

__global__ void __launch_bounds__(256) flash_kernel(
    const float* __restrict__ qkv, __half* __restrict__ ao)
{
    extern __shared__ float sm[];
    float* Qs  = sm;
    float* KVs = sm + 64 * FLASH_PAD;
    float* Ps  = sm + 2 * 64 * FLASH_PAD;

    int qt  = blockIdx.x;
    int bh  = blockIdx.y;
    int b   = bh >> 4;
    int h   = bh & 15;
    int tid = threadIdx.x;
    int r   = tid >> 2;
    int c   = tid & 3;

    const size_t qkv_base = (size_t)b * Sdim * (3 * Ddim) + (size_t)h * 64;

    #pragma unroll
    for (int it = 0; it < 4; it++) {
        int idx = tid + it * 256;
        int rr = idx >> 4;
        int cc = (idx & 15) << 2;
        *(float4*)&Qs[rr * FLASH_PAD + cc] =
            *(const float4*)(qkv + qkv_base + (size_t)(qt * 64 + rr) * (3 * Ddim) + cc);
    }

    float m = -1e30f, l = 0.f;
    float acc[16];
    #pragma unroll
    for (int i = 0; i < 16; i++) acc[i] = 0.f;
    int qglob = qt * 64 + r;

    for (int kt = 0; kt <= qt; kt++) {
        __syncthreads();
        #pragma unroll
        for (int it = 0; it < 4; it++) {
            int idx = tid + it * 256;
            int rr = idx >> 4;
            int cc = (idx & 15) << 2;
            *(float4*)&KVs[rr * FLASH_PAD + cc] =
                *(const float4*)(qkv + qkv_base + Ddim +
                                 (size_t)(kt * 64 + rr) * (3 * Ddim) + cc);
        }
        __syncthreads();

        float s[16];
        #pragma unroll
        for (int i = 0; i < 16; i++) s[i] = 0.f;
        #pragma unroll
        for (int d4 = 0; d4 < 16; d4++) {
            float4 q4 = *(const float4*)&Qs[r * FLASH_PAD + d4 * 4];
            #pragma unroll
            for (int i = 0; i < 16; i++) {
                float4 k4 = *(const float4*)&KVs[(c * 16 + i) * FLASH_PAD + d4 * 4];
                s[i] += q4.x * k4.x + q4.y * k4.y + q4.z * k4.z + q4.w * k4.w;
            }
        }
        bool diag = (kt == qt);
        float tmax = -1e30f;
        #pragma unroll
        for (int i = 0; i < 16; i++) {
            s[i] *= 0.125f;
            if (diag && (kt * 64 + c * 16 + i) > qglob) s[i] = -1e30f;
            tmax = fmaxf(tmax, s[i]);
        }
        tmax = fmaxf(tmax, __shfl_xor_sync(0xffffffffu, tmax, 1));
        tmax = fmaxf(tmax, __shfl_xor_sync(0xffffffffu, tmax, 2));
        float mnew = fmaxf(m, tmax);
        float corr = __expf(m - mnew);
        float psum = 0.f;
        #pragma unroll
        for (int i = 0; i < 16; i++) {
            float p = __expf(s[i] - mnew);
            psum += p;
            Ps[r * FLASH_PAD + c * 16 + i] = p;
        }
        psum += __shfl_xor_sync(0xffffffffu, psum, 1);
        psum += __shfl_xor_sync(0xffffffffu, psum, 2);
        l = l * corr + psum;
        m = mnew;
        #pragma unroll
        for (int i = 0; i < 16; i++) acc[i] *= corr;
        __syncthreads();

        #pragma unroll
        for (int it = 0; it < 4; it++) {
            int idx = tid + it * 256;
            int rr = idx >> 4;
            int cc = (idx & 15) << 2;
            *(float4*)&KVs[rr * FLASH_PAD + cc] =
                *(const float4*)(qkv + qkv_base + 2 * Ddim +
                                 (size_t)(kt * 64 + rr) * (3 * Ddim) + cc);
        }
        __syncthreads();

        #pragma unroll 8
        for (int k = 0; k < 64; k++) {
            float p = Ps[r * FLASH_PAD + k];
            const float4* vr = (const float4*)&KVs[k * FLASH_PAD + c * 16];
            float4 v0 = vr[0], v1 = vr[1], v2 = vr[2], v3 = vr[3];
            acc[0]  += p * v0.x; acc[1]  += p * v0.y; acc[2]  += p * v0.z; acc[3]  += p * v0.w;
            acc[4]  += p * v1.x; acc[5]  += p * v1.y; acc[6]  += p * v1.z; acc[7]  += p * v1.w;
            acc[8]  += p * v2.x; acc[9]  += p * v2.y; acc[10] += p * v2.z; acc[11] += p * v2.w;
            acc[12] += p * v3.x; acc[13] += p * v3.y; acc[14] += p * v3.z; acc[15] += p * v3.w;
        }
    }

    float inv = 1.f / l;
    __half2* out = (__half2*)(ao + (size_t)(b * Sdim + qt * 64 + r) * Ddim
                              + h * 64 + c * 16);
    #pragma unroll
    for (int j = 0; j < 8; j++)
        out[j] = __floats2half2_rn(acc[2 * j] * inv, acc[2 * j + 1] * inv);
}

// ---------------------------------------------------------------------------
// Launch sequence
// ---------------------------------------------------------------------------
extern "C" void kernel_launch(void* const* d_in, const int* in_sizes, int n_in,
                              void* d_out, int out_size)
{
    const int*   ids    = (const int*)d_in[0];
    const float* wte    = (const float*)d_in[1];
    const float* wpe    = (const float*)d_in[2];
    const float* ln1_g  = (const float*)d_in[3];
    const float* ln1_b  = (const float*)d_in[4];
    const float* W_attn = (const float*)d_in[5];
    const float* b_attn = (const float*)d_in[6];
    const float* W_ap   = (const float*)d_in[7];
    const float* b_ap   = (const float*)d_in[8];
    const float* ln2_g  = (const float*)d_in[9];
    const float* ln2_b  = (const float*)d_in[10];
    const float* W_fc   = (const float*)d_in[11];
    const float* b_fc   = (const float*)d_in[12];
    const float* W_proj = (const float*)d_in[13];
    const float* b_proj = (const float*)d_in[14];
    const float* lnf_g  = (const float*)d_in[15];
    const float* lnf_b  = (const float*)d_in[16];
    const float* W_lm   = (const float*)d_in[17];
    float* out = (float*)d_out;

    float *h, *qkv;
    __half *x16, *ao16, *fc16, *wattn16, *wap16, *wfc16, *wproj16, *wlm16;
    cudaGetSymbolAddress((void**)&h,       g_h);
    cudaGetSymbolAddress((void**)&qkv,     g_qkv);
    cudaGetSymbolAddress((void**)&x16,     g_x16);
    cudaGetSymbolAddress((void**)&ao16,    g_ao16);
    cudaGetSymbolAddress((void**)&fc16,    g_fc16);
    cudaGetSymbolAddress((void**)&wattn16, g_wattn16);
    cudaGetSymbolAddress((void**)&wap16,   g_wap16);
    cudaGetSymbolAddress((void**)&wfc16,   g_wfc16);
    cudaGetSymbolAddress((void**)&wproj16, g_wproj16);
    cudaGetSymbolAddress((void**)&wlm16,   g_wlm16);

    cudaFuncSetAttribute(flash_kernel,
                         cudaFuncAttributeMaxDynamicSharedMemorySize, FLASH_SMEM);
    cudaFuncSetAttribute(gemm16_kernel<true, false, false, false>,
                         cudaFuncAttributeMaxDynamicSharedMemorySize, GSMEM);
    cudaFuncSetAttribute(gemm16_kernel<true, false, true, false>,
                         cudaFuncAttributeMaxDynamicSharedMemorySize, GSMEM);
    cudaFuncSetAttribute(gemm16_kernel<true, true, false, true>,
                         cudaFuncAttributeMaxDynamicSharedMemorySize, GSMEM);
    cudaFuncSetAttribute(gemm16_kernel<false, false, false, false>,
                         cudaFuncAttributeMaxDynamicSharedMemorySize, GSMEM);

    // weight conversions (independent; overlap on stream)
    conv16_kernel<<<dim3(2, Ddim), 256>>>(W_attn, wattn16, 3 * Ddim, 3 * Ddim);
    conv16_kernel<<<dim3(1, Ddim), 256>>>(W_ap,   wap16,   Ddim, Ddim);
    conv16_kernel<<<dim3(2, Ddim), 256>>>(W_fc,   wfc16,   4 * Ddim, 4 * Ddim);
    conv16_kernel<<<dim3(1, 4 * Ddim), 256>>>(W_proj, wproj16, Ddim, Ddim);
    conv16_kernel<<<dim3(25, Ddim), 256>>>(W_lm,  wlm16,   Vdim, VPAD);

    embed_kernel<<<Mrows, 256>>>(ids, wte, wpe, h);
    ln16_kernel<<<Mrows, 256>>>(h, ln1_g, ln1_b, x16);
    gemm16_kernel<true, false, false, false><<<dim3(32, 24), 256, GSMEM>>>(
        x16, wattn16, b_attn, nullptr, qkv, Mrows, 3 * Ddim, Ddim, 3 * Ddim);
    flash_kernel<<<dim3(32, 32), 256, FLASH_SMEM>>>(qkv, ao16);
    gemm16_kernel<true, false, true, false><<<dim3(32, 8), 256, GSMEM>>>(
        ao16, wap16, b_ap, h, h, Mrows, Ddim, Ddim, Ddim);
    ln16_kernel<<<Mrows, 256>>>(h, ln2_g, ln2_b, x16);
    gemm16_kernel<true, true, false, true><<<dim3(32, 32), 256, GSMEM>>>(
        x16, wfc16, b_fc, nullptr, fc16, Mrows, 4 * Ddim, Ddim, 4 * Ddim);
    gemm16_kernel<true, false, true, false><<<dim3(32, 8), 256, GSMEM>>>(
        fc16, wproj16, b_proj, h, h, Mrows, Ddim, 4 * Ddim, Ddim);
    ln16_kernel<<<Mrows, 256>>>(h, lnf_g, lnf_b, x16);
    gemm16_kernel<false, false, false, false><<<dim3(32, 393), 256, GSMEM>>>(
        x16, wlm16, nullptr, nullptr, out, Mrows, Vdim, Ddim, VPAD);
}

// round 7
// speedup vs baseline: 7.7799x; 2.6066x over previous
#include <cuda_runtime.h>
#include <cuda_fp16.h>
#include <math.h>
#include <stdint.h>

// Problem dims (fixed)
#define Bdim 2
#define Sdim 2048
#define Ddim 1024
#define Vdim 50257
#define VPAD 50304            // 393*128
#define Mrows (Bdim * Sdim)   // 4096

// ---------------------------------------------------------------------------
// Scratch (device globals — no runtime allocation allowed)
// ---------------------------------------------------------------------------
__device__ float  g_h[(size_t)Mrows * Ddim];           // residual (fp32)
__device__ __half g_qkv16[(size_t)Mrows * 3 * Ddim];   // qkv (fp16)
__device__ __half g_x16[(size_t)Mrows * Ddim];         // LN out
__device__ __half g_ao16[(size_t)Mrows * Ddim];        // attn out
__device__ __half g_fc16[(size_t)Mrows * 4 * Ddim];    // gelu out
__device__ __half g_wattn16[(size_t)Ddim * 3 * Ddim];
__device__ __half g_wap16[(size_t)Ddim * Ddim];
__device__ __half g_wfc16[(size_t)Ddim * 4 * Ddim];
__device__ __half g_wproj16[(size_t)4 * Ddim * Ddim];
__device__ __half g_wlm16[(size_t)Ddim * VPAD];

__device__ __forceinline__ uint32_t smem_u32(const void* p) {
    uint32_t a;
    asm("{ .reg .u64 t; cvta.to.shared.u64 t, %1; cvt.u32.u64 %0, t; }"
        : "=r"(a) : "l"(p));
    return a;
}
__device__ __forceinline__ float gelu_new_f(float x) {
    float t = tanhf(0.7978845608028654f * (x + 0.044715f * x * x * x));
    return 0.5f * x * (1.0f + t);
}

#define LDSM4(r0, r1, r2, r3, a) \
    asm volatile("ldmatrix.sync.aligned.m8n8.x4.shared.b16 {%0,%1,%2,%3}, [%4];" \
        : "=r"(r0), "=r"(r1), "=r"(r2), "=r"(r3) : "r"(a))
#define LDSM4T(r0, r1, r2, r3, a) \
    asm volatile("ldmatrix.sync.aligned.m8n8.x4.trans.shared.b16 {%0,%1,%2,%3}, [%4];" \
        : "=r"(r0), "=r"(r1), "=r"(r2), "=r"(r3) : "r"(a))
#define MMA16816(d, a, b0, b1) \
    asm volatile("mma.sync.aligned.m16n8k16.row.col.f32.f16.f16.f32 " \
        "{%0,%1,%2,%3}, {%4,%5,%6,%7}, {%8,%9}, {%0,%1,%2,%3};" \
        : "+f"((d)[0]), "+f"((d)[1]), "+f"((d)[2]), "+f"((d)[3]) \
        : "r"((a)[0]), "r"((a)[1]), "r"((a)[2]), "r"((a)[3]), \
          "r"(b0), "r"(b1))

// ---------------------------------------------------------------------------
// fp32 -> fp16 weight conversion with optional column padding (zero fill)
// ---------------------------------------------------------------------------
__global__ void __launch_bounds__(256) conv16_kernel(
    const float* __restrict__ src, __half* __restrict__ dst, int N, int Np)
{
    int k   = blockIdx.y;
    int col = (blockIdx.x * 256 + threadIdx.x) * 8;
    if (col >= Np) return;
    __half h[8];
    #pragma unroll
    for (int j = 0; j < 8; j++) {
        int n = col + j;
        h[j] = (n < N) ? __float2half_rn(src[(size_t)k * N + n]) : __half(0.f);
    }
    *(uint4*)(dst + (size_t)k * Np + col) = *(uint4*)h;
}

// ---------------------------------------------------------------------------
// Embedding (fp32)
// ---------------------------------------------------------------------------
__global__ void __launch_bounds__(256) embed_kernel(
    const int* __restrict__ ids, const float* __restrict__ wte,
    const float* __restrict__ wpe, float* __restrict__ h)
{
    int row = blockIdx.x;
    int s   = row & (Sdim - 1);
    int id  = ids[row];
    const float4* te = (const float4*)(wte + (size_t)id * Ddim);
    const float4* pe = (const float4*)(wpe + (size_t)s * Ddim);
    float4* out = (float4*)(h + (size_t)row * Ddim);
    int t = threadIdx.x;
    float4 a = te[t], b = pe[t];
    out[t] = make_float4(a.x + b.x, a.y + b.y, a.z + b.z, a.w + b.w);
}

// ---------------------------------------------------------------------------
// LayerNorm (fp32 in) -> fp16 out
// ---------------------------------------------------------------------------
__global__ void __launch_bounds__(256) ln16_kernel(
    const float* __restrict__ in, const float* __restrict__ g,
    const float* __restrict__ b, __half* __restrict__ out)
{
    int row = blockIdx.x;
    int t = threadIdx.x;
    const float4* xp = (const float4*)(in + (size_t)row * Ddim);
    float4 v = xp[t];
    float s = v.x + v.y + v.z + v.w;
    float q = v.x * v.x + v.y * v.y + v.z * v.z + v.w * v.w;
    __shared__ float rs[8], rq[8];
    #pragma unroll
    for (int o = 16; o > 0; o >>= 1) {
        s += __shfl_xor_sync(0xffffffffu, s, o);
        q += __shfl_xor_sync(0xffffffffu, q, o);
    }
    if ((t & 31) == 0) { rs[t >> 5] = s; rq[t >> 5] = q; }
    __syncthreads();
    if (t == 0) {
        float S = 0.f, Q = 0.f;
        #pragma unroll
        for (int i = 0; i < 8; i++) { S += rs[i]; Q += rq[i]; }
        rs[0] = S; rq[0] = Q;
    }
    __syncthreads();
    float mu   = rs[0] * (1.f / Ddim);
    float var  = rq[0] * (1.f / Ddim) - mu * mu;
    float rstd = rsqrtf(var + 1e-5f);
    float4 gg = ((const float4*)g)[t];
    float4 bb = ((const float4*)b)[t];
    __half2* o = (__half2*)(out + (size_t)row * Ddim + t * 4);
    o[0] = __floats2half2_rn((v.x - mu) * rstd * gg.x + bb.x,
                             (v.y - mu) * rstd * gg.y + bb.y);
    o[1] = __floats2half2_rn((v.z - mu) * rstd * gg.z + bb.z,
                             (v.w - mu) * rstd * gg.w + bb.w);
}

// ---------------------------------------------------------------------------
// fp16 tensor-core GEMM (unchanged from R6; verified)
// ---------------------------------------------------------------------------
#define APh 40
#define BPh 136
#define ASZ (128 * APh)
#define BSZ (32 * BPh)
#define STGh (ASZ + BSZ)
#define GSMEM (3 * STGh * 2)

template<bool HAS_BIAS, bool DO_GELU, bool HAS_RES, bool OUT16>
__global__ void __launch_bounds__(256, 2) gemm16_kernel(
    const __half* __restrict__ A, const __half* __restrict__ W,
    const float* __restrict__ bias, const float* __restrict__ res,
    void* __restrict__ Cv, int M, int N, int K, int ldw)
{
    extern __shared__ __half sh[];
    const uint32_t sb = smem_u32(sh);

    const int tid  = threadIdx.x;
    const int wid  = tid >> 5;
    const int lane = tid & 31;
    const int wm   = (wid >> 2) * 64;
    const int wn   = (wid & 3) * 32;
    const int lr   = lane >> 2;
    const int lc   = lane & 3;
    const int bm   = blockIdx.x * 128;
    const int bn   = blockIdx.y * 128;

    const int am  = tid >> 2, akc = tid & 3;
    const int bk  = tid >> 4, bnc = tid & 15;

    auto issue = [&](int kb) {
        const int s = kb % 3;
        const uint32_t as = sb + (uint32_t)(s * STGh) * 2;
        const uint32_t bs = as + ASZ * 2;
        const int k0 = kb * 32;
        #pragma unroll
        for (int i = 0; i < 2; i++) {
            int m = am + i * 64;
            const __half* src = A + (size_t)(bm + m) * K + k0 + akc * 8;
            uint32_t dst = as + (uint32_t)(m * APh + akc * 8) * 2;
            asm volatile("cp.async.cg.shared.global [%0], [%1], 16;"
                         :: "r"(dst), "l"(src));
        }
        #pragma unroll
        for (int i = 0; i < 2; i++) {
            int k = bk + i * 16;
            const __half* src = W + (size_t)(k0 + k) * ldw + bn + bnc * 8;
            uint32_t dst = bs + (uint32_t)(k * BPh + bnc * 8) * 2;
            asm volatile("cp.async.cg.shared.global [%0], [%1], 16;"
                         :: "r"(dst), "l"(src));
        }
        asm volatile("cp.async.commit_group;");
    };

    float acc[4][4][4];
    #pragma unroll
    for (int i = 0; i < 4; i++)
        #pragma unroll
        for (int j = 0; j < 4; j++)
            #pragma unroll
            for (int e = 0; e < 4; e++) acc[i][j][e] = 0.f;

    const int nk = K / 32;
    issue(0);
    issue(1);

    for (int kb = 0; kb < nk; kb++) {
        if (kb + 1 < nk) asm volatile("cp.async.wait_group 1;");
        else             asm volatile("cp.async.wait_group 0;");
        __syncthreads();
        if (kb + 2 < nk) issue(kb + 2);

        const int s = kb % 3;
        const uint32_t as = sb + (uint32_t)(s * STGh) * 2;
        const uint32_t bs = as + ASZ * 2;

        #pragma unroll
        for (int ks = 0; ks < 2; ks++) {
            const int kk = ks * 16;
            uint32_t afr[4][4];
            #pragma unroll
            for (int mt = 0; mt < 4; mt++) {
                uint32_t a = as + (uint32_t)((wm + mt * 16 + (lane & 15)) * APh
                                             + kk + 8 * (lane >> 4)) * 2;
                LDSM4(afr[mt][0], afr[mt][1], afr[mt][2], afr[mt][3], a);
            }
            uint32_t bfr[4][2];
            #pragma unroll
            for (int p = 0; p < 2; p++) {
                int ntp = p * 2;
                uint32_t a = bs + (uint32_t)((kk + (lane & 7) + 8 * ((lane >> 3) & 1)) * BPh
                                             + wn + (ntp + (lane >> 4)) * 8) * 2;
                LDSM4T(bfr[ntp][0], bfr[ntp][1], bfr[ntp + 1][0], bfr[ntp + 1][1], a);
            }
            #pragma unroll
            for (int mt = 0; mt < 4; mt++)
                #pragma unroll
                for (int nt = 0; nt < 4; nt++)
                    MMA16816(acc[mt][nt], afr[mt], bfr[nt][0], bfr[nt][1]);
        }
    }

    float* Cf = (float*)Cv;
    __half* Ch = (__half*)Cv;
    #pragma unroll
    for (int mt = 0; mt < 4; mt++) {
        int row0 = bm + wm + mt * 16 + lr;
        #pragma unroll
        for (int nt = 0; nt < 4; nt++) {
            int col0 = bn + wn + nt * 8 + lc * 2;
            #pragma unroll
            for (int e = 0; e < 4; e++) {
                int row = row0 + (e >= 2 ? 8 : 0);
                int col = col0 + (e & 1);
                if (col < N) {
                    float v = acc[mt][nt][e];
                    if (HAS_BIAS) v += bias[col];
                    if (DO_GELU)  v = gelu_new_f(v);
                    size_t off = (size_t)row * (size_t)N + col;
                    if (HAS_RES)  v += res[off];
                    if (OUT16) Ch[off] = __float2half_rn(v);
                    else       Cf[off] = v;
                }
            }
        }
    }
}

// ---------------------------------------------------------------------------
// Tensor-core flash attention (causal). fp16 mma, fp32 softmax.
// Q tile 128x64 per CTA (8 warps x 16 rows), K/V tiles 64x64, 2-stage cp.async.
// Smem pitch 72 halves (144B = 9 chunks -> LDSM conflict-free).
// ---------------------------------------------------------------------------
#define FP 72
#define FLASH16_SMEM ((128 * FP + 4 * 64 * FP) * 2)   // 55296 B

__global__ void __launch_bounds__(256, 1) flashtc_kernel(
    const __half* __restrict__ qkv, __half* __restrict__ ao)
{
    extern __shared__ __half fsm[];
    const uint32_t sb   = smem_u32(fsm);
    const uint32_t qs_b = sb;
    const uint32_t ks_b = sb + 128 * FP * 2;
    const uint32_t vs_b = ks_b + 2 * 64 * FP * 2;
    __half* Qs = fsm;

    const int qt  = (int)gridDim.x - 1 - (int)blockIdx.x;  // longest first
    const int bh  = blockIdx.y;
    const int b   = bh >> 4;
    const int h   = bh & 15;
    const int tid = threadIdx.x;
    const int wid = tid >> 5;
    const int lane = tid & 31;
    const int lr  = lane >> 2;
    const int lc  = lane & 3;
    const size_t base = (size_t)b * Sdim * 3072 + (size_t)h * 64;

    // ---- load Q tile (scale by 1/8 during fill; exact in fp16) ----
    const __half2 kscale = __floats2half2_rn(0.125f, 0.125f);
    #pragma unroll
    for (int i = 0; i < 4; i++) {
        int task = tid + i * 256;          // 128 rows x 8 chunks
        int row = task >> 3, ch = task & 7;
        uint4 u = *(const uint4*)(qkv + base + (size_t)(qt * 128 + row) * 3072 + ch * 8);
        __half2* hp = (__half2*)&u;
        #pragma unroll
        for (int j = 0; j < 4; j++) hp[j] = __hmul2(hp[j], kscale);
        *(uint4*)&Qs[row * FP + ch * 8] = u;
    }

    auto issue = [&](int kt) {
        const int s = kt & 1;
        #pragma unroll
        for (int i = 0; i < 2; i++) {
            int task = tid + i * 256;      // 64 rows x 8 chunks
            int row = task >> 3, ch = task & 7;
            const __half* sk = qkv + base + 1024 + (size_t)(kt * 64 + row) * 3072 + ch * 8;
            const __half* sv = qkv + base + 2048 + (size_t)(kt * 64 + row) * 3072 + ch * 8;
            uint32_t dk = ks_b + (uint32_t)(s * 64 * FP + row * FP + ch * 8) * 2;
            uint32_t dv = vs_b + (uint32_t)(s * 64 * FP + row * FP + ch * 8) * 2;
            asm volatile("cp.async.cg.shared.global [%0], [%1], 16;" :: "r"(dk), "l"(sk));
            asm volatile("cp.async.cg.shared.global [%0], [%1], 16;" :: "r"(dv), "l"(sv));
        }
        asm volatile("cp.async.commit_group;");
    };

    const int ktn = 2 * qt + 2;
    issue(0);
    issue(1);
    __syncthreads();                       // Q smem visible to all warps

    // preload Q fragments (16 regs)
    uint32_t qf[4][4];
    {
        int row = wid * 16 + (lane & 15);
        int cof = 8 * (lane >> 4);
        #pragma unroll
        for (int kc = 0; kc < 4; kc++) {
            uint32_t a = qs_b + (uint32_t)(row * FP + kc * 16 + cof) * 2;
            LDSM4(qf[kc][0], qf[kc][1], qf[kc][2], qf[kc][3], a);
        }
    }

    float o[8][4];
    #pragma unroll
    for (int nt = 0; nt < 8; nt++)
        #pragma unroll
        for (int e = 0; e < 4; e++) o[nt][e] = 0.f;
    float m0 = -1e30f, m1 = -1e30f, l0 = 0.f, l1 = 0.f;
    const int qg0 = qt * 128 + wid * 16 + lr;

    for (int kt = 0; kt < ktn; kt++) {
        if (kt + 1 < ktn) asm volatile("cp.async.wait_group 1;");
        else              asm volatile("cp.async.wait_group 0;");
        __syncthreads();

        const int s = kt & 1;
        const uint32_t kb_ = ks_b + (uint32_t)(s * 64 * FP) * 2;
        const uint32_t vb_ = vs_b + (uint32_t)(s * 64 * FP) * 2;

        // ---- scores: S[16,64] = Qw @ K^T (pre-scaled) ----
        float sc[8][4];
        #pragma unroll
        for (int nt = 0; nt < 8; nt++)
            #pragma unroll
            for (int e = 0; e < 4; e++) sc[nt][e] = 0.f;
        const int krow = (lane & 7) + 8 * (lane >> 4);
        const int koff = 8 * ((lane >> 3) & 1);
        #pragma unroll
        for (int kc = 0; kc < 4; kc++) {
            #pragma unroll
            for (int np = 0; np < 4; np++) {
                uint32_t a = kb_ + (uint32_t)((np * 16 + krow) * FP + kc * 16 + koff) * 2;
                uint32_t b0, b1, b2, b3;
                LDSM4(b0, b1, b2, b3, a);
                MMA16816(sc[2 * np], qf[kc], b0, b1);
                MMA16816(sc[2 * np + 1], qf[kc], b2, b3);
            }
        }

        // ---- mask + online softmax ----
        const bool diag = (kt >= 2 * qt);
        float tmax0 = -1e30f, tmax1 = -1e30f;
        #pragma unroll
        for (int nt = 0; nt < 8; nt++) {
            #pragma unroll
            for (int e = 0; e < 4; e++) {
                if (diag) {
                    int key = kt * 64 + nt * 8 + 2 * lc + (e & 1);
                    int qg  = qg0 + (e >= 2 ? 8 : 0);
                    if (key > qg) sc[nt][e] = -1e30f;
                }
                if (e < 2) tmax0 = fmaxf(tmax0, sc[nt][e]);
                else       tmax1 = fmaxf(tmax1, sc[nt][e]);
            }
        }
        tmax0 = fmaxf(tmax0, __shfl_xor_sync(0xffffffffu, tmax0, 1));
        tmax0 = fmaxf(tmax0, __shfl_xor_sync(0xffffffffu, tmax0, 2));
        tmax1 = fmaxf(tmax1, __shfl_xor_sync(0xffffffffu, tmax1, 1));
        tmax1 = fmaxf(tmax1, __shfl_xor_sync(0xffffffffu, tmax1, 2));
        float mn0 = fmaxf(m0, tmax0), mn1 = fmaxf(m1, tmax1);
        float cr0 = __expf(m0 - mn0), cr1 = __expf(m1 - mn1);
        float ps0 = 0.f, ps1 = 0.f;
        #pragma unroll
        for (int nt = 0; nt < 8; nt++) {
            sc[nt][0] = __expf(sc[nt][0] - mn0);
            sc[nt][1] = __expf(sc[nt][1] - mn0);
            sc[nt][2] = __expf(sc[nt][2] - mn1);
            sc[nt][3] = __expf(sc[nt][3] - mn1);
            ps0 += sc[nt][0] + sc[nt][1];
            ps1 += sc[nt][2] + sc[nt][3];
        }
        ps0 += __shfl_xor_sync(0xffffffffu, ps0, 1);
        ps0 += __shfl_xor_sync(0xffffffffu, ps0, 2);
        ps1 += __shfl_xor_sync(0xffffffffu, ps1, 1);
        ps1 += __shfl_xor_sync(0xffffffffu, ps1, 2);
        l0 = l0 * cr0 + ps0;  m0 = mn0;
        l1 = l1 * cr1 + ps1;  m1 = mn1;
        #pragma unroll
        for (int nt = 0; nt < 8; nt++) {
            o[nt][0] *= cr0; o[nt][1] *= cr0;
            o[nt][2] *= cr1; o[nt][3] *= cr1;
        }

        // ---- P fragments (register pack; FA2 identity) ----
        uint32_t pf[4][4];
        #pragma unroll
        for (int kc = 0; kc < 4; kc++) {
            __half2 h0 = __floats2half2_rn(sc[2 * kc][0], sc[2 * kc][1]);
            __half2 h1 = __floats2half2_rn(sc[2 * kc][2], sc[2 * kc][3]);
            __half2 h2 = __floats2half2_rn(sc[2 * kc + 1][0], sc[2 * kc + 1][1]);
            __half2 h3 = __floats2half2_rn(sc[2 * kc + 1][2], sc[2 * kc + 1][3]);
            pf[kc][0] = *(uint32_t*)&h0;
            pf[kc][1] = *(uint32_t*)&h1;
            pf[kc][2] = *(uint32_t*)&h2;
            pf[kc][3] = *(uint32_t*)&h3;
        }

        // ---- O += P @ V ----
        const int vrow = (lane & 7) + 8 * ((lane >> 3) & 1);
        const int vcof = (lane >> 4);
        #pragma unroll
        for (int kc = 0; kc < 4; kc++) {
            #pragma unroll
            for (int np = 0; np < 4; np++) {
                uint32_t a = vb_ + (uint32_t)((kc * 16 + vrow) * FP + (np * 2 + vcof) * 8) * 2;
                uint32_t b0, b1, b2, b3;
                LDSM4T(b0, b1, b2, b3, a);
                MMA16816(o[2 * np], pf[kc], b0, b1);
                MMA16816(o[2 * np + 1], pf[kc], b2, b3);
            }
        }

        if (kt + 2 < ktn) {
            __syncthreads();               // all warps done reading stage s
            issue(kt + 2);
        }
    }

    // ---- write O (fp16) ----
    float i0 = 1.f / l0, i1 = 1.f / l1;
    size_t r0 = (size_t)(b * Sdim + qt * 128 + wid * 16 + lr) * Ddim + h * 64;
    size_t r1 = r0 + 8 * Ddim;
    #pragma unroll
    for (int nt = 0; nt < 8; nt++) {
        int col = nt * 8 + 2 * lc;
        *(__half2*)(ao + r0 + col) = __floats2half2_rn(o[nt][0] * i0, o[nt][1] * i0);
        *(__half2*)(ao + r1 + col) = __floats2half2_rn(o[nt][2] * i1, o[nt][3] * i1);
    }
}

// ---------------------------------------------------------------------------
// Launch sequence
// ---------------------------------------------------------------------------
extern "C" void kernel_launch(void* const* d_in, const int* in_sizes, int n_in,
                              void* d_out, int out_size)
{
    const int*   ids    = (const int*)d_in[0];
    const float* wte    = (const float*)d_in[1];
    const float* wpe    = (const float*)d_in[2];
    const float* ln1_g  = (const float*)d_in[3];
    const float* ln1_b  = (const float*)d_in[4];
    const float* W_attn = (const float*)d_in[5];
    const float* b_attn = (const float*)d_in[6];
    const float* W_ap   = (const float*)d_in[7];
    const float* b_ap   = (const float*)d_in[8];
    const float* ln2_g  = (const float*)d_in[9];
    const float* ln2_b  = (const float*)d_in[10];
    const float* W_fc   = (const float*)d_in[11];
    const float* b_fc   = (const float*)d_in[12];
    const float* W_proj = (const float*)d_in[13];
    const float* b_proj = (const float*)d_in[14];
    const float* lnf_g  = (const float*)d_in[15];
    const float* lnf_b  = (const float*)d_in[16];
    const float* W_lm   = (const float*)d_in[17];
    float* out = (float*)d_out;

    float *h;
    __half *qkv16, *x16, *ao16, *fc16, *wattn16, *wap16, *wfc16, *wproj16, *wlm16;
    cudaGetSymbolAddress((void**)&h,       g_h);
    cudaGetSymbolAddress((void**)&qkv16,   g_qkv16);
    cudaGetSymbolAddress((void**)&x16,     g_x16);
    cudaGetSymbolAddress((void**)&ao16,    g_ao16);
    cudaGetSymbolAddress((void**)&fc16,    g_fc16);
    cudaGetSymbolAddress((void**)&wattn16, g_wattn16);
    cudaGetSymbolAddress((void**)&wap16,   g_wap16);
    cudaGetSymbolAddress((void**)&wfc16,   g_wfc16);
    cudaGetSymbolAddress((void**)&wproj16, g_wproj16);
    cudaGetSymbolAddress((void**)&wlm16,   g_wlm16);

    cudaFuncSetAttribute(flashtc_kernel,
                         cudaFuncAttributeMaxDynamicSharedMemorySize, FLASH16_SMEM);
    cudaFuncSetAttribute(gemm16_kernel<true, false, false, true>,
                         cudaFuncAttributeMaxDynamicSharedMemorySize, GSMEM);
    cudaFuncSetAttribute(gemm16_kernel<true, false, true, false>,
                         cudaFuncAttributeMaxDynamicSharedMemorySize, GSMEM);
    cudaFuncSetAttribute(gemm16_kernel<true, true, false, true>,
                         cudaFuncAttributeMaxDynamicSharedMemorySize, GSMEM);
    cudaFuncSetAttribute(gemm16_kernel<false, false, false, false>,
                         cudaFuncAttributeMaxDynamicSharedMemorySize, GSMEM);

    // weight conversions
    conv16_kernel<<<dim3(2, Ddim), 256>>>(W_attn, wattn16, 3 * Ddim, 3 * Ddim);
    conv16_kernel<<<dim3(1, Ddim), 256>>>(W_ap,   wap16,   Ddim, Ddim);
    conv16_kernel<<<dim3(2, Ddim), 256>>>(W_fc,   wfc16,   4 * Ddim, 4 * Ddim);
    conv16_kernel<<<dim3(1, 4 * Ddim), 256>>>(W_proj, wproj16, Ddim, Ddim);
    conv16_kernel<<<dim3(25, Ddim), 256>>>(W_lm,  wlm16,   Vdim, VPAD);

    embed_kernel<<<Mrows, 256>>>(ids, wte, wpe, h);
    ln16_kernel<<<Mrows, 256>>>(h, ln1_g, ln1_b, x16);
    gemm16_kernel<true, false, false, true><<<dim3(32, 24), 256, GSMEM>>>(
        x16, wattn16, b_attn, nullptr, qkv16, Mrows, 3 * Ddim, Ddim, 3 * Ddim);
    flashtc_kernel<<<dim3(16, 32), 256, FLASH16_SMEM>>>(qkv16, ao16);
    gemm16_kernel<true, false, true, false><<<dim3(32, 8), 256, GSMEM>>>(
        ao16, wap16, b_ap, h, h, Mrows, Ddim, Ddim, Ddim);
    ln16_kernel<<<Mrows, 256>>>(h, ln2_g, ln2_b, x16);
    gemm16_kernel<true, true, false, true><<<dim3(32, 32), 256, GSMEM>>>(
        x16, wfc16, b_fc, nullptr, fc16, Mrows, 4 * Ddim, Ddim, 4 * Ddim);
    gemm16_kernel<true, false, true, false><<<dim3(32, 8), 256, GSMEM>>>(
        fc16, wproj16, b_proj, h, h, Mrows, Ddim, 4 * Ddim, Ddim);
    ln16_kernel<<<Mrows, 256>>>(h, lnf_g, lnf_b, x16);
    gemm16_kernel<false, false, false, false><<<dim3(32, 393), 256, GSMEM>>>(
        x16, wlm16, nullptr, nullptr, out, Mrows, Vdim, Ddim, VPAD);
}